// round 2
// baseline (speedup 1.0000x reference)
#include <cuda_runtime.h>
#include <cstdint>

// ---------------- problem constants ----------------
#define BT   8192      // B*T
#define TT   1024      // T
#define BB   8         // B
#define C1   1024
#define C3   3072
#define C4   4096
#define NH   16
#define HD   64
#define LN_EPS 1e-5f

// ---------------- scratch (device globals; no allocation) ----------------
__device__ float g_ln1[(size_t)BT * C1];
__device__ float g_qkv[(size_t)BT * C3];
__device__ float g_att[(size_t)BT * C1];
__device__ float g_x1 [(size_t)BT * C1];
__device__ float g_ln2[(size_t)BT * C1];
__device__ float g_h  [(size_t)BT * C4];

// ---------------- LayerNorm: one block per row ----------------
__global__ void ln_kernel(const float* __restrict__ x,
                          const float* __restrict__ w,
                          const float* __restrict__ b,
                          float* __restrict__ y)
{
    const int row = blockIdx.x;
    const float4* xr = (const float4*)(x + (size_t)row * C1);
    float4 v = xr[threadIdx.x];                       // 256 threads * 4 = 1024
    float s  = v.x + v.y + v.z + v.w;
    float s2 = v.x*v.x + v.y*v.y + v.z*v.z + v.w*v.w;

    // block reduce (8 warps)
    __shared__ float red[2][8];
    for (int off = 16; off > 0; off >>= 1) {
        s  += __shfl_down_sync(0xffffffffu, s,  off);
        s2 += __shfl_down_sync(0xffffffffu, s2, off);
    }
    int warp = threadIdx.x >> 5, lane = threadIdx.x & 31;
    if (lane == 0) { red[0][warp] = s; red[1][warp] = s2; }
    __syncthreads();
    float ts = 0.f, ts2 = 0.f;
#pragma unroll
    for (int i = 0; i < 8; i++) { ts += red[0][i]; ts2 += red[1][i]; }
    float mean = ts * (1.0f / C1);
    float var  = ts2 * (1.0f / C1) - mean * mean;
    float inv  = rsqrtf(var + LN_EPS);

    const float4 wv = ((const float4*)w)[threadIdx.x];
    const float4 bv = ((const float4*)b)[threadIdx.x];
    float4 o;
    o.x = (v.x - mean) * inv * wv.x + bv.x;
    o.y = (v.y - mean) * inv * wv.y + bv.y;
    o.z = (v.z - mean) * inv * wv.z + bv.z;
    o.w = (v.w - mean) * inv * wv.w + bv.w;
    ((float4*)(y + (size_t)row * C1))[threadIdx.x] = o;
}

// ---------------- SGEMM: C = A[M,K] @ B[K,N] + bias, optional epilogue ----
// EPI: 0 = none, 1 = residual add (res), 2 = tanh-GELU
// block tile 128x128, K-tile 8, 256 threads, 8x8 per-thread microtile
template<int EPI>
__global__ void gemm_kernel(const float* __restrict__ A,
                            const float* __restrict__ B,
                            const float* __restrict__ bias,
                            const float* __restrict__ res,
                            float* __restrict__ C,
                            int M, int N, int K)
{
    __shared__ float As[8][128];
    __shared__ float Bs[8][132];   // pad: 132*4 bytes keeps 16B alignment

    const int tid  = threadIdx.x;
    const long row0 = (long)blockIdx.y * 128;
    const long col0 = (long)blockIdx.x * 128;

    const int ar = tid >> 1;          // 0..127
    const int ak = (tid & 1) * 4;     // 0 or 4
    const int bk = tid >> 5;          // 0..7
    const int bc = (tid & 31) * 4;    // 0..124

    const int tr = (tid >> 4) * 8;    // thread row within tile
    const int tc = (tid & 15) * 8;    // thread col within tile

    float acc[8][8];
#pragma unroll
    for (int i = 0; i < 8; i++)
#pragma unroll
        for (int j = 0; j < 8; j++) acc[i][j] = 0.f;

    for (int k0 = 0; k0 < K; k0 += 8) {
        float4 a = *(const float4*)(A + (row0 + ar) * K + k0 + ak);
        As[ak + 0][ar] = a.x; As[ak + 1][ar] = a.y;
        As[ak + 2][ar] = a.z; As[ak + 3][ar] = a.w;
        float4 bvec = *(const float4*)(B + (long)(k0 + bk) * N + col0 + bc);
        *(float4*)&Bs[bk][bc] = bvec;
        __syncthreads();

#pragma unroll
        for (int kk = 0; kk < 8; kk++) {
            float ra[8], rb[8];
#pragma unroll
            for (int i = 0; i < 8; i++) ra[i] = As[kk][tr + i];
#pragma unroll
            for (int j = 0; j < 8; j++) rb[j] = Bs[kk][tc + j];
#pragma unroll
            for (int i = 0; i < 8; i++)
#pragma unroll
                for (int j = 0; j < 8; j++) acc[i][j] = fmaf(ra[i], rb[j], acc[i][j]);
        }
        __syncthreads();
    }

    // epilogue
#pragma unroll
    for (int i = 0; i < 8; i++) {
        const long crow = row0 + tr + i;
        float vals[8];
#pragma unroll
        for (int j = 0; j < 8; j++) {
            float v = acc[i][j] + bias[col0 + tc + j];
            if (EPI == 1) v += res[crow * N + col0 + tc + j];
            if (EPI == 2) {
                float t = v + 0.044715f * v * v * v;
                v = 0.5f * v * (1.0f + tanhf(0.79788456080286536f * t));
            }
            vals[j] = v;
        }
        float* cp = C + crow * N + col0 + tc;
        *(float4*)(cp + 0) = make_float4(vals[0], vals[1], vals[2], vals[3]);
        *(float4*)(cp + 4) = make_float4(vals[4], vals[5], vals[6], vals[7]);
    }
}

// ---------------- causal flash attention (fp32) ----------------
// grid: (T/64 qblocks, NH heads, BB batch), 128 threads
// Q tile 64x64, K/V tiles 32x64, online softmax with -1e30 masking.
__global__ void attn_kernel(const float* __restrict__ qkv, float* __restrict__ y)
{
    const int qb = blockIdx.x, h = blockIdx.y, b = blockIdx.z;
    const int qbase = qb * 64;
    const float* base = qkv + (size_t)b * TT * C3;

    __shared__ float sq[64][65];
    __shared__ float sk[32][65];
    __shared__ float sv[32][65];
    __shared__ float ss[64][33];
    __shared__ float sm[64], sl[64], salpha[64];

    const int tid = threadIdx.x;
    const int r0  = (tid >> 3) * 4;      // 16 row groups * 4 rows
    const int cS  = (tid & 7) * 4;       // S micro-cols (4)
    const int cO  = (tid & 7) * 8;       // O micro-cols (8)

    // load Q tile (64 rows x 64 dims), float4 coalesced
    for (int i = tid; i < 64 * 16; i += 128) {
        int r = i >> 4, c4 = (i & 15) * 4;
        float4 v = *(const float4*)(base + (size_t)(qbase + r) * C3 + h * HD + c4);
        sq[r][c4 + 0] = v.x; sq[r][c4 + 1] = v.y; sq[r][c4 + 2] = v.z; sq[r][c4 + 3] = v.w;
    }
    if (tid < 64) { sm[tid] = -1e30f; sl[tid] = 0.f; }

    float acc_o[4][8];
#pragma unroll
    for (int i = 0; i < 4; i++)
#pragma unroll
        for (int j = 0; j < 8; j++) acc_o[i][j] = 0.f;

    __syncthreads();

    const int kmax = (qbase + 63) >> 5;   // inclusive
    for (int kb = 0; kb <= kmax; kb++) {
        const int kbase = kb * 32;
        // load K,V tiles (32 x 64 each)
        for (int i = tid; i < 32 * 16; i += 128) {
            int r = i >> 4, c4 = (i & 15) * 4;
            const float* kp = base + (size_t)(kbase + r) * C3 + C1 + h * HD + c4;
            float4 kv = *(const float4*)kp;
            float4 vv = *(const float4*)(kp + C1);
            sk[r][c4 + 0] = kv.x; sk[r][c4 + 1] = kv.y; sk[r][c4 + 2] = kv.z; sk[r][c4 + 3] = kv.w;
            sv[r][c4 + 0] = vv.x; sv[r][c4 + 1] = vv.y; sv[r][c4 + 2] = vv.z; sv[r][c4 + 3] = vv.w;
        }
        __syncthreads();

        // S = Q K^T (64x32), each thread 4x4
        float accs[4][4];
#pragma unroll
        for (int i = 0; i < 4; i++)
#pragma unroll
            for (int j = 0; j < 4; j++) accs[i][j] = 0.f;
#pragma unroll 8
        for (int d = 0; d < 64; d++) {
            float a[4], kvals[4];
#pragma unroll
            for (int i = 0; i < 4; i++) a[i] = sq[r0 + i][d];
#pragma unroll
            for (int j = 0; j < 4; j++) kvals[j] = sk[cS + j][d];
#pragma unroll
            for (int i = 0; i < 4; i++)
#pragma unroll
                for (int j = 0; j < 4; j++) accs[i][j] = fmaf(a[i], kvals[j], accs[i][j]);
        }
        const bool needMask = (kbase + 31 > qbase);
#pragma unroll
        for (int i = 0; i < 4; i++)
#pragma unroll
            for (int j = 0; j < 4; j++) {
                float sval = accs[i][j] * 0.125f;   // 1/sqrt(64)
                if (needMask && (kbase + cS + j > qbase + r0 + i)) sval = -1e30f;
                ss[r0 + i][cS + j] = sval;
            }
        __syncthreads();

        // online softmax: 2 threads per row, 16 cols each
        {
            const int row = tid >> 1;
            const int seg = (tid & 1) * 16;
            float lmax = -1e30f;
#pragma unroll
            for (int c = 0; c < 16; c++) lmax = fmaxf(lmax, ss[row][seg + c]);
            lmax = fmaxf(lmax, __shfl_xor_sync(0xffffffffu, lmax, 1));
            const float mold = sm[row];
            const float mnew = fmaxf(mold, lmax);
            float lsum = 0.f;
#pragma unroll
            for (int c = 0; c < 16; c++) {
                float p = __expf(ss[row][seg + c] - mnew);
                ss[row][seg + c] = p;
                lsum += p;
            }
            lsum += __shfl_xor_sync(0xffffffffu, lsum, 1);
            if ((tid & 1) == 0) {
                float alpha = __expf(mold - mnew);   // mold=mnew=-1e30 -> exp(0)=1, harmless (O==0)
                salpha[row] = alpha;
                sm[row] = mnew;
                sl[row] = sl[row] * alpha + lsum;
            }
        }
        __syncthreads();

        // O = O*alpha + P @ V  (64x64), each thread 4x8
#pragma unroll
        for (int i = 0; i < 4; i++) {
            float al = salpha[r0 + i];
#pragma unroll
            for (int j = 0; j < 8; j++) acc_o[i][j] *= al;
        }
#pragma unroll 4
        for (int d = 0; d < 32; d++) {
            float p[4], vvals[8];
#pragma unroll
            for (int i = 0; i < 4; i++) p[i] = ss[r0 + i][d];
#pragma unroll
            for (int j = 0; j < 8; j++) vvals[j] = sv[d][cO + j];
#pragma unroll
            for (int i = 0; i < 4; i++)
#pragma unroll
                for (int j = 0; j < 8; j++) acc_o[i][j] = fmaf(p[i], vvals[j], acc_o[i][j]);
        }
        __syncthreads();
    }

    // write y[b, qrow, h*64 + c]
#pragma unroll
    for (int i = 0; i < 4; i++) {
        const float invl = 1.0f / sl[r0 + i];
        float* yp = y + ((size_t)b * TT + qbase + r0 + i) * C1 + h * HD + cO;
        float4 o0 = make_float4(acc_o[i][0]*invl, acc_o[i][1]*invl, acc_o[i][2]*invl, acc_o[i][3]*invl);
        float4 o1 = make_float4(acc_o[i][4]*invl, acc_o[i][5]*invl, acc_o[i][6]*invl, acc_o[i][7]*invl);
        *(float4*)(yp + 0) = o0;
        *(float4*)(yp + 4) = o1;
    }
}

// ---------------- launcher ----------------
extern "C" void kernel_launch(void* const* d_in, const int* in_sizes, int n_in,
                              void* d_out, int out_size)
{
    const float* x      = (const float*)d_in[0];
    const float* ln1_w  = (const float*)d_in[1];
    const float* ln1_b  = (const float*)d_in[2];
    const float* w_qkv  = (const float*)d_in[3];
    const float* b_qkv  = (const float*)d_in[4];
    const float* w_o    = (const float*)d_in[5];
    const float* b_o    = (const float*)d_in[6];
    const float* ln2_w  = (const float*)d_in[7];
    const float* ln2_b  = (const float*)d_in[8];
    const float* w_fc   = (const float*)d_in[9];
    const float* b_fc   = (const float*)d_in[10];
    const float* w_proj = (const float*)d_in[11];
    const float* b_proj = (const float*)d_in[12];
    float* out = (float*)d_out;

    float *ln1, *qkv, *att, *x1, *ln2, *hbuf;
    cudaGetSymbolAddress((void**)&ln1,  g_ln1);
    cudaGetSymbolAddress((void**)&qkv,  g_qkv);
    cudaGetSymbolAddress((void**)&att,  g_att);
    cudaGetSymbolAddress((void**)&x1,   g_x1);
    cudaGetSymbolAddress((void**)&ln2,  g_ln2);
    cudaGetSymbolAddress((void**)&hbuf, g_h);

    // 1. LN1
    ln_kernel<<<BT, 256>>>(x, ln1_w, ln1_b, ln1);
    // 2. QKV GEMM: [8192,1024] @ [1024,3072]
    gemm_kernel<0><<<dim3(C3 / 128, BT / 128), 256>>>(ln1, w_qkv, b_qkv, nullptr, qkv, BT, C3, C1);
    // 3. causal attention
    attn_kernel<<<dim3(TT / 64, NH, BB), 128>>>(qkv, att);
    // 4. O-proj + residual(x)
    gemm_kernel<1><<<dim3(C1 / 128, BT / 128), 256>>>(att, w_o, b_o, x, x1, BT, C1, C1);
    // 5. LN2
    ln_kernel<<<BT, 256>>>(x1, ln2_w, ln2_b, ln2);
    // 6. FC + GELU: [8192,1024] @ [1024,4096]
    gemm_kernel<2><<<dim3(C4 / 128, BT / 128), 256>>>(ln2, w_fc, b_fc, nullptr, hbuf, BT, C4, C1);
    // 7. down-proj + residual(x1): [8192,4096] @ [4096,1024]
    gemm_kernel<1><<<dim3(C1 / 128, BT / 128), 256>>>(hbuf, w_proj, b_proj, x1, out, BT, C1, C4);
}

// round 4
// speedup vs baseline: 1.9313x; 1.9313x over previous
#include <cuda_runtime.h>
#include <cuda_bf16.h>
#include <cstdint>

// ---------------- problem constants ----------------
#define BT   8192      // B*T
#define TT   1024      // T
#define BB   8         // B
#define C1   1024
#define C3   3072
#define C4   4096
#define NH   16
#define HD   64
#define LN_EPS 1e-5f

// GEMM tiling (mma.sync path)
#define BM   128
#define BN   128
#define BK   32
#define NTH  256
#define STAGES 3
#define ROWB 80                         // bytes per smem row (32 bf16 + 8 pad)
#define STAGE_BYTES (2 * BM * ROWB)     // A tile + B tile = 20480
#define GEMM_SMEM_BYTES (STAGES * STAGE_BYTES)   // 61440

// ---------------- scratch (device globals; no allocation) ----------------
__device__ __align__(128) float g_qkv[(size_t)BT * C3];
__device__ __align__(128) float g_x1 [(size_t)BT * C1];
// bf16 extended (hi/lo concat along K: A=[hi,lo,hi], B(t)=[hi,hi,lo])
__device__ __align__(128) __nv_bfloat16 g_wqkv_t[(size_t)C3 * 3 * C1];
__device__ __align__(128) __nv_bfloat16 g_wo_t  [(size_t)C1 * 3 * C1];
__device__ __align__(128) __nv_bfloat16 g_wfc_t [(size_t)C4 * 3 * C1];
__device__ __align__(128) __nv_bfloat16 g_wpr_t [(size_t)C1 * 3 * C4];
__device__ __align__(128) __nv_bfloat16 g_ln1e  [(size_t)BT * 3 * C1];
__device__ __align__(128) __nv_bfloat16 g_atte  [(size_t)BT * 3 * C1];
__device__ __align__(128) __nv_bfloat16 g_ln2e  [(size_t)BT * 3 * C1];
__device__ __align__(128) __nv_bfloat16 g_he    [(size_t)BT * 3 * C4];

// ---------------- helpers ----------------
__device__ __forceinline__ uint32_t smem_u32(const void* p) {
    uint32_t a;
    asm("{ .reg .u64 t; cvta.to.shared.u64 t, %1; cvt.u32.u64 %0, t; }" : "=r"(a) : "l"(p));
    return a;
}
__device__ __forceinline__ void cp_async16(uint32_t saddr, const void* g) {
    asm volatile("cp.async.cg.shared.global [%0], [%1], 16;" :: "r"(saddr), "l"(g));
}
#define CP_COMMIT() asm volatile("cp.async.commit_group;" ::: "memory")
#define CP_WAIT(n)  asm volatile("cp.async.wait_group %0;" :: "n"(n) : "memory")

__device__ __forceinline__ void mma16816(float* c, const uint32_t* a, const uint32_t* b) {
    asm volatile("mma.sync.aligned.m16n8k16.row.col.f32.bf16.bf16.f32 "
        "{%0,%1,%2,%3}, {%4,%5,%6,%7}, {%8,%9}, {%0,%1,%2,%3};"
        : "+f"(c[0]), "+f"(c[1]), "+f"(c[2]), "+f"(c[3])
        : "r"(a[0]), "r"(a[1]), "r"(a[2]), "r"(a[3]), "r"(b[0]), "r"(b[1]));
}

__device__ __forceinline__ void split_bf16(float v, __nv_bfloat16& hi, __nv_bfloat16& lo) {
    hi = __float2bfloat16(v);
    lo = __float2bfloat16(v - __bfloat162float(hi));
}

// ---------------- weight transpose + hi/lo split ----------------
// W[K,N] fp32  ->  Wt[N, 3K] bf16, segments [hi, hi, lo]
__global__ void conv_w_kernel(const float* __restrict__ W, __nv_bfloat16* __restrict__ Wt, int K, int N)
{
    __shared__ float tile[32][33];
    const int k0 = blockIdx.y * 32, n0 = blockIdx.x * 32;
    const int tx = threadIdx.x, ty = threadIdx.y;   // 32 x 8
#pragma unroll
    for (int i = 0; i < 32; i += 8)
        tile[ty + i][tx] = W[(long)(k0 + ty + i) * N + n0 + tx];
    __syncthreads();
#pragma unroll
    for (int i = 0; i < 32; i += 8) {
        const int n = ty + i;
        float v = tile[tx][n];
        __nv_bfloat16 hi, lo; split_bf16(v, hi, lo);
        long base = (long)(n0 + n) * (3L * K) + k0 + tx;
        Wt[base]          = hi;
        Wt[base + K]      = hi;
        Wt[base + 2L * K] = lo;
    }
}

// ---------------- LayerNorm -> extended bf16 [row, 3*C1] -------------
__global__ void ln_ext_kernel(const float* __restrict__ x,
                              const float* __restrict__ w,
                              const float* __restrict__ b,
                              __nv_bfloat16* __restrict__ ye)
{
    const int row = blockIdx.x;
    const float4* xr = (const float4*)(x + (size_t)row * C1);
    float4 v = xr[threadIdx.x];
    float s  = v.x + v.y + v.z + v.w;
    float s2 = v.x*v.x + v.y*v.y + v.z*v.z + v.w*v.w;
    __shared__ float red[2][8];
    for (int off = 16; off > 0; off >>= 1) {
        s  += __shfl_down_sync(0xffffffffu, s,  off);
        s2 += __shfl_down_sync(0xffffffffu, s2, off);
    }
    int warp = threadIdx.x >> 5, lane = threadIdx.x & 31;
    if (lane == 0) { red[0][warp] = s; red[1][warp] = s2; }
    __syncthreads();
    float ts = 0.f, ts2 = 0.f;
#pragma unroll
    for (int i = 0; i < 8; i++) { ts += red[0][i]; ts2 += red[1][i]; }
    float mean = ts * (1.0f / C1);
    float var  = ts2 * (1.0f / C1) - mean * mean;
    float inv  = rsqrtf(var + LN_EPS);

    const float4 wv = ((const float4*)w)[threadIdx.x];
    const float4 bv = ((const float4*)b)[threadIdx.x];
    float o0 = (v.x - mean) * inv * wv.x + bv.x;
    float o1 = (v.y - mean) * inv * wv.y + bv.y;
    float o2 = (v.z - mean) * inv * wv.z + bv.z;
    float o3 = (v.w - mean) * inv * wv.w + bv.w;
    __nv_bfloat16 h0,l0,h1,l1,h2,l2,h3,l3;
    split_bf16(o0,h0,l0); split_bf16(o1,h1,l1); split_bf16(o2,h2,l2); split_bf16(o3,h3,l3);
    size_t rb = (size_t)row * (3 * C1);
    int c4 = threadIdx.x * 4;
    __nv_bfloat162* p0 = (__nv_bfloat162*)(ye + rb + c4);
    p0[0] = __nv_bfloat162{h0, h1}; p0[1] = __nv_bfloat162{h2, h3};
    __nv_bfloat162* p1 = (__nv_bfloat162*)(ye + rb + C1 + c4);
    p1[0] = __nv_bfloat162{l0, l1}; p1[1] = __nv_bfloat162{l2, l3};
    __nv_bfloat162* p2 = (__nv_bfloat162*)(ye + rb + 2 * C1 + c4);
    p2[0] = __nv_bfloat162{h0, h1}; p2[1] = __nv_bfloat162{h2, h3};
}

// ---------------- mma.sync GEMM: D = A[M,Kext] @ Bt[N,Kext]^T + bias ----------
// EPI: 0 = fp32 out + bias; 1 = fp32 out + bias + residual; 2 = gelu -> ext bf16 out
// 256 threads, 8 warps as 4(m) x 2(n); warp tile 32x64; double/triple-buffered cp.async.
template<int EPI>
__global__ void __launch_bounds__(NTH)
mma_gemm(const __nv_bfloat16* __restrict__ A,
         const __nv_bfloat16* __restrict__ Bt,
         const float* __restrict__ bias,
         const float* __restrict__ res,
         float* __restrict__ Cf,
         __nv_bfloat16* __restrict__ Cext,
         int N, int Kext)
{
    extern __shared__ char smem[];
    const uint32_t sbase = smem_u32(smem);
    const int tid  = threadIdx.x;
    const int wid  = tid >> 5, lane = tid & 31;
    const int wm   = (wid & 3) * 32;        // warp row base within tile
    const int wn   = (wid >> 2) * 64;       // warp col base within tile

    const long row0 = (long)blockIdx.y * BM;
    const long col0 = (long)blockIdx.x * BN;
    const __nv_bfloat16* Ab = A  + row0 * Kext;
    const __nv_bfloat16* Bb = Bt + col0 * Kext;

    const int NKB = Kext / BK;

    // per-thread cp.async assignments: 2 chunks A + 2 chunks B per stage
    const int r_a = tid >> 1;               // 0..127 (two segs per row pair)
    // chunk o in {tid, tid+256}: row = o>>2, seg = o&3

    float acc[2][8][4];
#pragma unroll
    for (int mi = 0; mi < 2; mi++)
#pragma unroll
        for (int nj = 0; nj < 8; nj++)
#pragma unroll
            for (int q = 0; q < 4; q++) acc[mi][nj][q] = 0.f;
    (void)r_a;

    // ---- stage loader ----
    auto load_tile = [&](int buf, long k0) {
        const uint32_t abase = sbase + buf * STAGE_BYTES;
        const uint32_t bbase = abase + BM * ROWB;
#pragma unroll
        for (int t = 0; t < 2; t++) {
            int o = tid + t * NTH;          // 0..511
            int r = o >> 2, seg = o & 3;
            cp_async16(abase + r * ROWB + seg * 16, Ab + (long)r * Kext + k0 + seg * 8);
        }
#pragma unroll
        for (int t = 0; t < 2; t++) {
            int o = tid + t * NTH;
            int r = o >> 2, seg = o & 3;
            cp_async16(bbase + r * ROWB + seg * 16, Bb + (long)r * Kext + k0 + seg * 8);
        }
        CP_COMMIT();
    };

    // prefetch STAGES-1 tiles
#pragma unroll
    for (int s = 0; s < STAGES - 1; s++) load_tile(s, (long)s * BK);

    for (int kb = 0; kb < NKB; kb++) {
        CP_WAIT(STAGES - 2);
        __syncthreads();

        const int buf = kb % STAGES;
        const char* sa = smem + buf * STAGE_BYTES;
        const char* sb = sa + BM * ROWB;

#pragma unroll
        for (int ks = 0; ks < 2; ks++) {
            const int kw = ks * 16;
            const int kk = kw + (lane & 3) * 2;     // bf16 element offset
            uint32_t afr[2][4];
#pragma unroll
            for (int mi = 0; mi < 2; mi++) {
                const int r = wm + mi * 16 + (lane >> 2);
                afr[mi][0] = *(const uint32_t*)(sa + (r    ) * ROWB + kk * 2);
                afr[mi][1] = *(const uint32_t*)(sa + (r + 8) * ROWB + kk * 2);
                afr[mi][2] = *(const uint32_t*)(sa + (r    ) * ROWB + (kk + 8) * 2);
                afr[mi][3] = *(const uint32_t*)(sa + (r + 8) * ROWB + (kk + 8) * 2);
            }
            uint32_t bfr[8][2];
#pragma unroll
            for (int nj = 0; nj < 8; nj++) {
                const int n = wn + nj * 8 + (lane >> 2);
                bfr[nj][0] = *(const uint32_t*)(sb + n * ROWB + kk * 2);
                bfr[nj][1] = *(const uint32_t*)(sb + n * ROWB + (kk + 8) * 2);
            }
#pragma unroll
            for (int mi = 0; mi < 2; mi++)
#pragma unroll
                for (int nj = 0; nj < 8; nj++)
                    mma16816(acc[mi][nj], afr[mi], bfr[nj]);
        }
        __syncthreads();

        const int nk = kb + STAGES - 1;
        if (nk < NKB) load_tile(nk % STAGES, (long)nk * BK);
    }

    // ---- epilogue ----
#pragma unroll
    for (int mi = 0; mi < 2; mi++) {
#pragma unroll
        for (int rr = 0; rr < 2; rr++) {
            const long R = row0 + wm + mi * 16 + (lane >> 2) + rr * 8;
#pragma unroll
            for (int nj = 0; nj < 8; nj++) {
                const long CC = col0 + wn + nj * 8 + (lane & 3) * 2;
                float v0 = acc[mi][nj][rr * 2 + 0] + bias[CC];
                float v1 = acc[mi][nj][rr * 2 + 1] + bias[CC + 1];
                if (EPI == 1) {
                    const float2 rv = *(const float2*)(res + R * N + CC);
                    v0 += rv.x; v1 += rv.y;
                }
                if (EPI == 2) {
                    float t0 = v0 + 0.044715f * v0 * v0 * v0;
                    float t1 = v1 + 0.044715f * v1 * v1 * v1;
                    v0 = v0 / (1.0f + __expf(-1.5957691216057308f * t0));
                    v1 = v1 / (1.0f + __expf(-1.5957691216057308f * t1));
                    __nv_bfloat16 h0, l0, h1, l1;
                    split_bf16(v0, h0, l0); split_bf16(v1, h1, l1);
                    __nv_bfloat16* pe = Cext + R * (3L * N);
                    *(__nv_bfloat162*)(pe + CC)          = __nv_bfloat162{h0, h1};
                    *(__nv_bfloat162*)(pe + N + CC)      = __nv_bfloat162{l0, l1};
                    *(__nv_bfloat162*)(pe + 2L * N + CC) = __nv_bfloat162{h0, h1};
                } else {
                    *(float2*)(Cf + R * N + CC) = make_float2(v0, v1);
                }
            }
        }
    }
}

// ---------------- causal flash attention (fp32), ext bf16 output ------------
__global__ void attn_kernel(const float* __restrict__ qkv, __nv_bfloat16* __restrict__ ye)
{
    const int qb = blockIdx.x, h = blockIdx.y, b = blockIdx.z;
    const int qbase = qb * 64;
    const float* base = qkv + (size_t)b * TT * C3;

    __shared__ float sq[64][65];
    __shared__ float sk[32][65];
    __shared__ float sv[32][65];
    __shared__ float ss[64][33];
    __shared__ float sm[64], sl[64], salpha[64];

    const int tid = threadIdx.x;
    const int r0  = (tid >> 3) * 4;
    const int cS  = (tid & 7) * 4;
    const int cO  = (tid & 7) * 8;

    for (int i = tid; i < 64 * 16; i += 128) {
        int r = i >> 4, c4 = (i & 15) * 4;
        float4 v = *(const float4*)(base + (size_t)(qbase + r) * C3 + h * HD + c4);
        sq[r][c4 + 0] = v.x; sq[r][c4 + 1] = v.y; sq[r][c4 + 2] = v.z; sq[r][c4 + 3] = v.w;
    }
    if (tid < 64) { sm[tid] = -1e30f; sl[tid] = 0.f; }

    float acc_o[4][8];
#pragma unroll
    for (int i = 0; i < 4; i++)
#pragma unroll
        for (int j = 0; j < 8; j++) acc_o[i][j] = 0.f;

    __syncthreads();

    const int kmax = (qbase + 63) >> 5;
    for (int kb = 0; kb <= kmax; kb++) {
        const int kbase = kb * 32;
        for (int i = tid; i < 32 * 16; i += 128) {
            int r = i >> 4, c4 = (i & 15) * 4;
            const float* kp = base + (size_t)(kbase + r) * C3 + C1 + h * HD + c4;
            float4 kv = *(const float4*)kp;
            float4 vv = *(const float4*)(kp + C1);
            sk[r][c4 + 0] = kv.x; sk[r][c4 + 1] = kv.y; sk[r][c4 + 2] = kv.z; sk[r][c4 + 3] = kv.w;
            sv[r][c4 + 0] = vv.x; sv[r][c4 + 1] = vv.y; sv[r][c4 + 2] = vv.z; sv[r][c4 + 3] = vv.w;
        }
        __syncthreads();

        float accs[4][4];
#pragma unroll
        for (int i = 0; i < 4; i++)
#pragma unroll
            for (int j = 0; j < 4; j++) accs[i][j] = 0.f;
#pragma unroll 8
        for (int d = 0; d < 64; d++) {
            float a[4], kvals[4];
#pragma unroll
            for (int i = 0; i < 4; i++) a[i] = sq[r0 + i][d];
#pragma unroll
            for (int j = 0; j < 4; j++) kvals[j] = sk[cS + j][d];
#pragma unroll
            for (int i = 0; i < 4; i++)
#pragma unroll
                for (int j = 0; j < 4; j++) accs[i][j] = fmaf(a[i], kvals[j], accs[i][j]);
        }
        const bool needMask = (kbase + 31 > qbase);
#pragma unroll
        for (int i = 0; i < 4; i++)
#pragma unroll
            for (int j = 0; j < 4; j++) {
                float sval = accs[i][j] * 0.125f;
                if (needMask && (kbase + cS + j > qbase + r0 + i)) sval = -1e30f;
                ss[r0 + i][cS + j] = sval;
            }
        __syncthreads();

        {
            const int row = tid >> 1;
            const int seg = (tid & 1) * 16;
            float lmax = -1e30f;
#pragma unroll
            for (int c = 0; c < 16; c++) lmax = fmaxf(lmax, ss[row][seg + c]);
            lmax = fmaxf(lmax, __shfl_xor_sync(0xffffffffu, lmax, 1));
            const float mold = sm[row];
            const float mnew = fmaxf(mold, lmax);
            float lsum = 0.f;
#pragma unroll
            for (int c = 0; c < 16; c++) {
                float p = __expf(ss[row][seg + c] - mnew);
                ss[row][seg + c] = p;
                lsum += p;
            }
            lsum += __shfl_xor_sync(0xffffffffu, lsum, 1);
            if ((tid & 1) == 0) {
                float alpha = __expf(mold - mnew);
                salpha[row] = alpha;
                sm[row] = mnew;
                sl[row] = sl[row] * alpha + lsum;
            }
        }
        __syncthreads();

#pragma unroll
        for (int i = 0; i < 4; i++) {
            float al = salpha[r0 + i];
#pragma unroll
            for (int j = 0; j < 8; j++) acc_o[i][j] *= al;
        }
#pragma unroll 4
        for (int d = 0; d < 32; d++) {
            float p[4], vvals[8];
#pragma unroll
            for (int i = 0; i < 4; i++) p[i] = ss[r0 + i][d];
#pragma unroll
            for (int j = 0; j < 8; j++) vvals[j] = sv[d][cO + j];
#pragma unroll
            for (int i = 0; i < 4; i++)
#pragma unroll
                for (int j = 0; j < 8; j++) acc_o[i][j] = fmaf(p[i], vvals[j], acc_o[i][j]);
        }
        __syncthreads();
    }

    // write ext bf16: segments [hi, lo, hi] along 3*C1
#pragma unroll
    for (int i = 0; i < 4; i++) {
        const float invl = 1.0f / sl[r0 + i];
        __nv_bfloat16* yp = ye + ((size_t)(b * TT + qbase + r0 + i)) * (3 * C1) + h * HD + cO;
        __nv_bfloat16 hi[8], lo[8];
#pragma unroll
        for (int j = 0; j < 8; j++) split_bf16(acc_o[i][j] * invl, hi[j], lo[j]);
#pragma unroll
        for (int j = 0; j < 8; j += 2) {
            *(__nv_bfloat162*)(yp + j)            = __nv_bfloat162{hi[j], hi[j+1]};
            *(__nv_bfloat162*)(yp + C1 + j)       = __nv_bfloat162{lo[j], lo[j+1]};
            *(__nv_bfloat162*)(yp + 2 * C1 + j)   = __nv_bfloat162{hi[j], hi[j+1]};
        }
    }
}

// ---------------- launcher ----------------
extern "C" void kernel_launch(void* const* d_in, const int* in_sizes, int n_in,
                              void* d_out, int out_size)
{
    const float* x      = (const float*)d_in[0];
    const float* ln1_w  = (const float*)d_in[1];
    const float* ln1_b  = (const float*)d_in[2];
    const float* w_qkv  = (const float*)d_in[3];
    const float* b_qkv  = (const float*)d_in[4];
    const float* w_o    = (const float*)d_in[5];
    const float* b_o    = (const float*)d_in[6];
    const float* ln2_w  = (const float*)d_in[7];
    const float* ln2_b  = (const float*)d_in[8];
    const float* w_fc   = (const float*)d_in[9];
    const float* b_fc   = (const float*)d_in[10];
    const float* w_proj = (const float*)d_in[11];
    const float* b_proj = (const float*)d_in[12];
    float* out = (float*)d_out;

    float *qkv, *x1;
    __nv_bfloat16 *wqkv_t, *wo_t, *wfc_t, *wpr_t, *ln1e, *atte, *ln2e, *he;
    cudaGetSymbolAddress((void**)&qkv,   g_qkv);
    cudaGetSymbolAddress((void**)&x1,    g_x1);
    cudaGetSymbolAddress((void**)&wqkv_t, g_wqkv_t);
    cudaGetSymbolAddress((void**)&wo_t,   g_wo_t);
    cudaGetSymbolAddress((void**)&wfc_t,  g_wfc_t);
    cudaGetSymbolAddress((void**)&wpr_t,  g_wpr_t);
    cudaGetSymbolAddress((void**)&ln1e,   g_ln1e);
    cudaGetSymbolAddress((void**)&atte,   g_atte);
    cudaGetSymbolAddress((void**)&ln2e,   g_ln2e);
    cudaGetSymbolAddress((void**)&he,     g_he);

    cudaFuncSetAttribute(mma_gemm<0>, cudaFuncAttributeMaxDynamicSharedMemorySize, GEMM_SMEM_BYTES);
    cudaFuncSetAttribute(mma_gemm<1>, cudaFuncAttributeMaxDynamicSharedMemorySize, GEMM_SMEM_BYTES);
    cudaFuncSetAttribute(mma_gemm<2>, cudaFuncAttributeMaxDynamicSharedMemorySize, GEMM_SMEM_BYTES);

    // weight transpose + split (Bt layouts, segments [hi, hi, lo])
    conv_w_kernel<<<dim3(C3 / 32, C1 / 32), dim3(32, 8)>>>(w_qkv,  wqkv_t, C1, C3);
    conv_w_kernel<<<dim3(C1 / 32, C1 / 32), dim3(32, 8)>>>(w_o,    wo_t,   C1, C1);
    conv_w_kernel<<<dim3(C4 / 32, C1 / 32), dim3(32, 8)>>>(w_fc,   wfc_t,  C1, C4);
    conv_w_kernel<<<dim3(C1 / 32, C4 / 32), dim3(32, 8)>>>(w_proj, wpr_t,  C4, C1);

    // 1. LN1 -> ext
    ln_ext_kernel<<<BT, 256>>>(x, ln1_w, ln1_b, ln1e);
    // 2. QKV GEMM -> fp32 qkv
    mma_gemm<0><<<dim3(C3 / BN, BT / BM), NTH, GEMM_SMEM_BYTES>>>(ln1e, wqkv_t, b_qkv, nullptr, qkv, nullptr, C3, 3 * C1);
    // 3. attention -> ext
    attn_kernel<<<dim3(TT / 64, NH, BB), 128>>>(qkv, atte);
    // 4. O-proj + residual(x) -> fp32 x1
    mma_gemm<1><<<dim3(C1 / BN, BT / BM), NTH, GEMM_SMEM_BYTES>>>(atte, wo_t, b_o, x, x1, nullptr, C1, 3 * C1);
    // 5. LN2 -> ext
    ln_ext_kernel<<<BT, 256>>>(x1, ln2_w, ln2_b, ln2e);
    // 6. FC + GELU -> ext bf16 h
    mma_gemm<2><<<dim3(C4 / BN, BT / BM), NTH, GEMM_SMEM_BYTES>>>(ln2e, wfc_t, b_fc, nullptr, nullptr, he, C4, 3 * C1);
    // 7. down-proj + residual(x1) -> out
    mma_gemm<1><<<dim3(C1 / BN, BT / BM), NTH, GEMM_SMEM_BYTES>>>(he, wpr_t, b_proj, x1, out, nullptr, C1, 3 * C4);
}

// round 7
// speedup vs baseline: 3.6444x; 1.8870x over previous
#include <cuda_runtime.h>
#include <cuda_fp16.h>
#include <cstdint>

// ---------------- problem constants ----------------
#define BT   8192      // B*T
#define TT   1024      // T
#define BB   8         // B
#define C1   1024
#define C3   3072
#define C4   4096
#define NH   16
#define HD   64
#define LN_EPS 1e-5f

// GEMM tiling (mma.sync path)
#define BM   128
#define BN   128
#define BK   32
#define NTH  256
#define STAGES 3
#define ROWB 80                         // bytes per smem row (32 f16 + 8 pad)
#define STAGE_BYTES (2 * BM * ROWB)     // A tile + B tile = 20480
#define GEMM_SMEM_BYTES (STAGES * STAGE_BYTES)   // 61440

// ---------------- scratch (device globals; no allocation) ----------------
__device__ __align__(128) float g_qkv[(size_t)BT * C3];
__device__ __align__(128) float g_x1 [(size_t)BT * C1];
// fp16 extended (2-term: activations A=[hi,lo], weights Bt=[hi,hi])
__device__ __align__(128) __half g_wqkv_t[(size_t)C3 * 2 * C1];
__device__ __align__(128) __half g_wo_t  [(size_t)C1 * 2 * C1];
__device__ __align__(128) __half g_wfc_t [(size_t)C4 * 2 * C1];
__device__ __align__(128) __half g_wpr_t [(size_t)C1 * 2 * C4];
__device__ __align__(128) __half g_ln1e  [(size_t)BT * 2 * C1];
__device__ __align__(128) __half g_atte  [(size_t)BT * 2 * C1];
__device__ __align__(128) __half g_ln2e  [(size_t)BT * 2 * C1];
__device__ __align__(128) __half g_he    [(size_t)BT * 2 * C4];

// ---------------- helpers ----------------
__device__ __forceinline__ uint32_t smem_u32(const void* p) {
    uint32_t a;
    asm("{ .reg .u64 t; cvta.to.shared.u64 t, %1; cvt.u32.u64 %0, t; }" : "=r"(a) : "l"(p));
    return a;
}
__device__ __forceinline__ void cp_async16(uint32_t saddr, const void* g) {
    asm volatile("cp.async.cg.shared.global [%0], [%1], 16;" :: "r"(saddr), "l"(g));
}
#define CP_COMMIT() asm volatile("cp.async.commit_group;" ::: "memory")
#define CP_WAIT(n)  asm volatile("cp.async.wait_group %0;" :: "n"(n) : "memory")

__device__ __forceinline__ void ldsm_x4(uint32_t* r, uint32_t addr) {
    asm volatile("ldmatrix.sync.aligned.m8n8.x4.shared.b16 {%0,%1,%2,%3}, [%4];"
        : "=r"(r[0]), "=r"(r[1]), "=r"(r[2]), "=r"(r[3]) : "r"(addr));
}
__device__ __forceinline__ void ldsm_x4_t(uint32_t* r, uint32_t addr) {
    asm volatile("ldmatrix.sync.aligned.m8n8.x4.trans.shared.b16 {%0,%1,%2,%3}, [%4];"
        : "=r"(r[0]), "=r"(r[1]), "=r"(r[2]), "=r"(r[3]) : "r"(addr));
}
__device__ __forceinline__ void mma16816(float* c, const uint32_t* a, const uint32_t* b) {
    asm volatile("mma.sync.aligned.m16n8k16.row.col.f32.f16.f16.f32 "
        "{%0,%1,%2,%3}, {%4,%5,%6,%7}, {%8,%9}, {%0,%1,%2,%3};"
        : "+f"(c[0]), "+f"(c[1]), "+f"(c[2]), "+f"(c[3])
        : "r"(a[0]), "r"(a[1]), "r"(a[2]), "r"(a[3]), "r"(b[0]), "r"(b[1]));
}
__device__ __forceinline__ void split_f16(float v, __half& hi, __half& lo) {
    hi = __float2half_rn(v);
    lo = __float2half_rn(v - __half2float(hi));
}
__device__ __forceinline__ uint32_t pack_h2(float a, float b) {
    __half2 h = __floats2half2_rn(a, b);
    return *(uint32_t*)&h;
}

// ---------------- weight transpose + fp16 ----------------
// W[K,N] fp32  ->  Wt[N, 2K] fp16, segments [hi, hi]
__global__ void conv_w_kernel(const float* __restrict__ W, __half* __restrict__ Wt, int K, int N)
{
    __shared__ float tile[32][33];
    const int k0 = blockIdx.y * 32, n0 = blockIdx.x * 32;
    const int tx = threadIdx.x, ty = threadIdx.y;   // 32 x 8
#pragma unroll
    for (int i = 0; i < 32; i += 8)
        tile[ty + i][tx] = W[(long)(k0 + ty + i) * N + n0 + tx];
    __syncthreads();
#pragma unroll
    for (int i = 0; i < 32; i += 8) {
        const int n = ty + i;
        __half hi = __float2half_rn(tile[tx][n]);
        long base = (long)(n0 + n) * (2L * K) + k0 + tx;
        Wt[base]     = hi;
        Wt[base + K] = hi;
    }
}

// ---------------- LayerNorm -> extended fp16 [row, 2*C1] -------------
__global__ void ln_ext_kernel(const float* __restrict__ x,
                              const float* __restrict__ w,
                              const float* __restrict__ b,
                              __half* __restrict__ ye)
{
    const int row = blockIdx.x;
    const float4* xr = (const float4*)(x + (size_t)row * C1);
    float4 v = xr[threadIdx.x];
    float s  = v.x + v.y + v.z + v.w;
    float s2 = v.x*v.x + v.y*v.y + v.z*v.z + v.w*v.w;
    __shared__ float red[2][8];
    for (int off = 16; off > 0; off >>= 1) {
        s  += __shfl_down_sync(0xffffffffu, s,  off);
        s2 += __shfl_down_sync(0xffffffffu, s2, off);
    }
    int warp = threadIdx.x >> 5, lane = threadIdx.x & 31;
    if (lane == 0) { red[0][warp] = s; red[1][warp] = s2; }
    __syncthreads();
    float ts = 0.f, ts2 = 0.f;
#pragma unroll
    for (int i = 0; i < 8; i++) { ts += red[0][i]; ts2 += red[1][i]; }
    float mean = ts * (1.0f / C1);
    float var  = ts2 * (1.0f / C1) - mean * mean;
    float inv  = rsqrtf(var + LN_EPS);

    const float4 wv = ((const float4*)w)[threadIdx.x];
    const float4 bv = ((const float4*)b)[threadIdx.x];
    float o0 = (v.x - mean) * inv * wv.x + bv.x;
    float o1 = (v.y - mean) * inv * wv.y + bv.y;
    float o2 = (v.z - mean) * inv * wv.z + bv.z;
    float o3 = (v.w - mean) * inv * wv.w + bv.w;
    __half h0,l0,h1,l1,h2,l2,h3,l3;
    split_f16(o0,h0,l0); split_f16(o1,h1,l1); split_f16(o2,h2,l2); split_f16(o3,h3,l3);
    size_t rb = (size_t)row * (2 * C1);
    int c4 = threadIdx.x * 4;
    __half2* p0 = (__half2*)(ye + rb + c4);
    p0[0] = __halves2half2(h0, h1); p0[1] = __halves2half2(h2, h3);
    __half2* p1 = (__half2*)(ye + rb + C1 + c4);
    p1[0] = __halves2half2(l0, l1); p1[1] = __halves2half2(l2, l3);
}

// ---------------- mma.sync GEMM: D = A[M,Kext] @ Bt[N,Kext]^T + bias ----------
// EPI: 0 = fp32 out + bias; 1 = fp32 out + bias + residual; 2 = gelu -> ext fp16 out
template<int EPI>
__global__ void __launch_bounds__(NTH)
mma_gemm(const __half* __restrict__ A,
         const __half* __restrict__ Bt,
         const float* __restrict__ bias,
         const float* __restrict__ res,
         float* __restrict__ Cf,
         __half* __restrict__ Cext,
         int N, int Kext)
{
    extern __shared__ char smem[];
    const uint32_t sbase = smem_u32(smem);
    const int tid  = threadIdx.x;
    const int wid  = tid >> 5, lane = tid & 31;
    const int wm   = (wid & 3) * 32;        // warp row base within tile
    const int wn   = (wid >> 2) * 64;       // warp col base within tile

    const long row0 = (long)blockIdx.y * BM;
    const long col0 = (long)blockIdx.x * BN;
    const __half* Ab = A  + row0 * Kext;
    const __half* Bb = Bt + col0 * Kext;

    const int NKB = Kext / BK;

    float acc[2][8][4];
#pragma unroll
    for (int mi = 0; mi < 2; mi++)
#pragma unroll
        for (int nj = 0; nj < 8; nj++)
#pragma unroll
            for (int q = 0; q < 4; q++) acc[mi][nj][q] = 0.f;

    // ldmatrix per-lane offsets
    const int grp = lane >> 3;
    const uint32_t a_off = (uint32_t)((wm + (grp & 1) * 8 + (lane & 7)) * ROWB + (grp >> 1) * 16);
    const uint32_t b_off = (uint32_t)(BM * ROWB + (wn + (grp >> 1) * 8 + (lane & 7)) * ROWB + (grp & 1) * 16);

    auto load_tile = [&](int buf, long k0) {
        const uint32_t abase = sbase + buf * STAGE_BYTES;
        const uint32_t bbase = abase + BM * ROWB;
#pragma unroll
        for (int t = 0; t < 2; t++) {
            int o = tid + t * NTH;          // 0..511
            int r = o >> 2, seg = o & 3;
            cp_async16(abase + r * ROWB + seg * 16, Ab + (long)r * Kext + k0 + seg * 8);
        }
#pragma unroll
        for (int t = 0; t < 2; t++) {
            int o = tid + t * NTH;
            int r = o >> 2, seg = o & 3;
            cp_async16(bbase + r * ROWB + seg * 16, Bb + (long)r * Kext + k0 + seg * 8);
        }
        CP_COMMIT();
    };

#pragma unroll
    for (int s = 0; s < STAGES - 1; s++) load_tile(s, (long)s * BK);

    for (int kb = 0; kb < NKB; kb++) {
        CP_WAIT(STAGES - 2);
        __syncthreads();

        const int buf = kb % STAGES;
        const uint32_t sbuf = sbase + buf * STAGE_BYTES;

#pragma unroll
        for (int ks = 0; ks < 2; ks++) {
            uint32_t afr[2][4];
#pragma unroll
            for (int mi = 0; mi < 2; mi++)
                ldsm_x4(afr[mi], sbuf + a_off + mi * 16 * ROWB + ks * 32);
            uint32_t bfr[8][2];
#pragma unroll
            for (int njp = 0; njp < 4; njp++) {
                uint32_t t[4];
                ldsm_x4(t, sbuf + b_off + njp * 16 * ROWB + ks * 32);
                bfr[2*njp][0] = t[0]; bfr[2*njp][1] = t[1];
                bfr[2*njp+1][0] = t[2]; bfr[2*njp+1][1] = t[3];
            }
#pragma unroll
            for (int mi = 0; mi < 2; mi++)
#pragma unroll
                for (int nj = 0; nj < 8; nj++)
                    mma16816(acc[mi][nj], afr[mi], bfr[nj]);
        }
        __syncthreads();

        const int nk = kb + STAGES - 1;
        if (nk < NKB) load_tile(nk % STAGES, (long)nk * BK);
    }

    // ---- epilogue ----
#pragma unroll
    for (int mi = 0; mi < 2; mi++) {
#pragma unroll
        for (int rr = 0; rr < 2; rr++) {
            const long R = row0 + wm + mi * 16 + (lane >> 2) + rr * 8;
#pragma unroll
            for (int nj = 0; nj < 8; nj++) {
                const long CC = col0 + wn + nj * 8 + (lane & 3) * 2;
                float v0 = acc[mi][nj][rr * 2 + 0] + bias[CC];
                float v1 = acc[mi][nj][rr * 2 + 1] + bias[CC + 1];
                if (EPI == 1) {
                    const float2 rv = *(const float2*)(res + R * N + CC);
                    v0 += rv.x; v1 += rv.y;
                }
                if (EPI == 2) {
                    float t0 = v0 + 0.044715f * v0 * v0 * v0;
                    float t1 = v1 + 0.044715f * v1 * v1 * v1;
                    v0 = v0 / (1.0f + __expf(-1.5957691216057308f * t0));
                    v1 = v1 / (1.0f + __expf(-1.5957691216057308f * t1));
                    __half h0, l0, h1, l1;
                    split_f16(v0, h0, l0); split_f16(v1, h1, l1);
                    __half* pe = Cext + R * (2L * N);
                    *(__half2*)(pe + CC)     = __halves2half2(h0, h1);
                    *(__half2*)(pe + N + CC) = __halves2half2(l0, l1);
                } else {
                    *(float2*)(Cf + R * N + CC) = make_float2(v0, v1);
                }
            }
        }
    }
}

// ---------------- tensor-core causal flash attention ------------
// grid (T/64, NH, B), 128 threads (4 warps x 16 q rows); 64-key tiles.
// S and PV via mma.sync fp16; softmax fp32 in registers; output -> ext fp16 [hi,lo].
#define AROW 72   // halves per smem row (64 + 8 pad)
__global__ void __launch_bounds__(128)
attn_kernel(const float* __restrict__ qkv, __half* __restrict__ ye)
{
    const int qb = blockIdx.x, h = blockIdx.y, b = blockIdx.z;
    const int q0g = qb * 64;
    const float* base = qkv + (size_t)b * TT * C3 + h * HD;

    __shared__ __half sq[64 * AROW];
    __shared__ __half sk[64 * AROW];
    __shared__ __half sv[64 * AROW];

    const int tid = threadIdx.x;
    const int wid = tid >> 5, lane = tid & 31;
    const int wq = wid * 16;                 // warp q-row base within block
    const int grp = lane >> 3;

    const uint32_t sqb = smem_u32(sq), skb = smem_u32(sk), svb = smem_u32(sv);

    // load Q (64 x 64 fp32 -> fp16)
#pragma unroll
    for (int t = 0; t < 8; t++) {
        int i = tid + t * 128;
        int r = i >> 4, c4 = (i & 15) * 4;
        float4 v = *(const float4*)(base + (size_t)(q0g + r) * C3 + c4);
        __half2* p = (__half2*)(sq + r * AROW + c4);
        p[0] = __floats2half2_rn(v.x, v.y);
        p[1] = __floats2half2_rn(v.z, v.w);
    }
    __syncthreads();

    // Q fragments: qf[kd][4], kd = d/16
    uint32_t qf[4][4];
    {
        const uint32_t qoff = (uint32_t)((wq + (grp & 1) * 8 + (lane & 7)) * AROW * 2 + (grp >> 1) * 16);
#pragma unroll
        for (int kd = 0; kd < 4; kd++)
            ldsm_x4(qf[kd], sqb + qoff + kd * 32);
    }

    float o[8][4];
#pragma unroll
    for (int i = 0; i < 8; i++)
#pragma unroll
        for (int q = 0; q < 4; q++) o[i][q] = 0.f;
    float m0 = -1e30f, m1 = -1e30f, l0 = 0.f, l1 = 0.f;

    const uint32_t kfoff = (uint32_t)(((grp >> 1) * 8 + (lane & 7)) * AROW * 2 + (grp & 1) * 16);
    const uint32_t vfoff = (uint32_t)(((grp & 1) * 8 + (lane & 7)) * AROW * 2 + (grp >> 1) * 16);

    for (int kt = 0; kt <= qb; kt++) {
        __syncthreads();
        // load K, V tiles (64 x 64 each)
#pragma unroll
        for (int t = 0; t < 8; t++) {
            int i = tid + t * 128;
            int r = i >> 4, c4 = (i & 15) * 4;
            const float* kp = base + (size_t)(kt * 64 + r) * C3 + C1 + c4;
            float4 kv = *(const float4*)kp;
            float4 vv = *(const float4*)(kp + C1);
            __half2* pk = (__half2*)(sk + r * AROW + c4);
            pk[0] = __floats2half2_rn(kv.x, kv.y);
            pk[1] = __floats2half2_rn(kv.z, kv.w);
            __half2* pv = (__half2*)(sv + r * AROW + c4);
            pv[0] = __floats2half2_rn(vv.x, vv.y);
            pv[1] = __floats2half2_rn(vv.z, vv.w);
        }
        __syncthreads();

        // S = Q K^T : 16 x 64 per warp
        float c[8][4];
#pragma unroll
        for (int nj = 0; nj < 8; nj++)
#pragma unroll
            for (int q = 0; q < 4; q++) c[nj][q] = 0.f;
#pragma unroll
        for (int kd = 0; kd < 4; kd++) {
#pragma unroll
            for (int njp = 0; njp < 4; njp++) {
                uint32_t t[4];
                ldsm_x4(t, skb + kfoff + njp * 16 * AROW * 2 + kd * 32);
                uint32_t bA[2] = {t[0], t[1]}, bB[2] = {t[2], t[3]};
                mma16816(c[2*njp],   qf[kd], bA);
                mma16816(c[2*njp+1], qf[kd], bB);
            }
        }

        // scale + causal mask (only diagonal tile needs masking)
        const int ra = q0g + wq + (lane >> 2);
        if (kt == qb) {
#pragma unroll
            for (int nj = 0; nj < 8; nj++) {
                const int cb = kt * 64 + nj * 8 + (lane & 3) * 2;
#pragma unroll
                for (int e = 0; e < 2; e++) {
                    c[nj][e]     = (cb + e > ra)     ? -1e30f : c[nj][e] * 0.125f;
                    c[nj][2 + e] = (cb + e > ra + 8) ? -1e30f : c[nj][2 + e] * 0.125f;
                }
            }
        } else {
#pragma unroll
            for (int nj = 0; nj < 8; nj++)
#pragma unroll
                for (int q = 0; q < 4; q++) c[nj][q] *= 0.125f;
        }

        // online softmax (rows ra: c0,c1 / ra+8: c2,c3; 4 lanes per row)
        float mxa = -1e30f, mxb = -1e30f;
#pragma unroll
        for (int nj = 0; nj < 8; nj++) {
            mxa = fmaxf(mxa, fmaxf(c[nj][0], c[nj][1]));
            mxb = fmaxf(mxb, fmaxf(c[nj][2], c[nj][3]));
        }
        mxa = fmaxf(mxa, __shfl_xor_sync(0xffffffffu, mxa, 1));
        mxa = fmaxf(mxa, __shfl_xor_sync(0xffffffffu, mxa, 2));
        mxb = fmaxf(mxb, __shfl_xor_sync(0xffffffffu, mxb, 1));
        mxb = fmaxf(mxb, __shfl_xor_sync(0xffffffffu, mxb, 2));
        const float mna = fmaxf(m0, mxa), mnb = fmaxf(m1, mxb);
        const float alpha_a = __expf(m0 - mna), alpha_b = __expf(m1 - mnb);
        m0 = mna; m1 = mnb;
        float suma = 0.f, sumb = 0.f;
#pragma unroll
        for (int nj = 0; nj < 8; nj++) {
            c[nj][0] = __expf(c[nj][0] - mna);
            c[nj][1] = __expf(c[nj][1] - mna);
            c[nj][2] = __expf(c[nj][2] - mnb);
            c[nj][3] = __expf(c[nj][3] - mnb);
            suma += c[nj][0] + c[nj][1];
            sumb += c[nj][2] + c[nj][3];
        }
        suma += __shfl_xor_sync(0xffffffffu, suma, 1);
        suma += __shfl_xor_sync(0xffffffffu, suma, 2);
        sumb += __shfl_xor_sync(0xffffffffu, sumb, 1);
        sumb += __shfl_xor_sync(0xffffffffu, sumb, 2);
        l0 = l0 * alpha_a + suma;
        l1 = l1 * alpha_b + sumb;
#pragma unroll
        for (int i = 0; i < 8; i++) {
            o[i][0] *= alpha_a; o[i][1] *= alpha_a;
            o[i][2] *= alpha_b; o[i][3] *= alpha_b;
        }

        // P fragments (fp16) : pf[ks][4], ks = key/16
        uint32_t pf[4][4];
#pragma unroll
        for (int ks = 0; ks < 4; ks++) {
            pf[ks][0] = pack_h2(c[2*ks][0],   c[2*ks][1]);
            pf[ks][1] = pack_h2(c[2*ks][2],   c[2*ks][3]);
            pf[ks][2] = pack_h2(c[2*ks+1][0], c[2*ks+1][1]);
            pf[ks][3] = pack_h2(c[2*ks+1][2], c[2*ks+1][3]);
        }

        // O += P @ V (V^T fragments via ldmatrix.trans)
#pragma unroll
        for (int ks = 0; ks < 4; ks++) {
#pragma unroll
            for (int dp = 0; dp < 4; dp++) {
                uint32_t t[4];
                ldsm_x4_t(t, svb + vfoff + ks * 16 * AROW * 2 + dp * 32);
                uint32_t bA[2] = {t[0], t[1]}, bB[2] = {t[2], t[3]};
                mma16816(o[2*dp],   pf[ks], bA);
                mma16816(o[2*dp+1], pf[ks], bB);
            }
        }
    }

    // epilogue: divide by l, split to [hi, lo] ext fp16
    const float invl0 = 1.0f / l0, invl1 = 1.0f / l1;
    const long rowg = (long)b * TT + q0g + wq + (lane >> 2);
#pragma unroll
    for (int i = 0; i < 8; i++) {
        const int colg = h * HD + i * 8 + (lane & 3) * 2;
        {
            float v0 = o[i][0] * invl0, v1 = o[i][1] * invl0;
            __half h0, lo0, h1, lo1;
            split_f16(v0, h0, lo0); split_f16(v1, h1, lo1);
            __half* yp = ye + rowg * (2L * C1) + colg;
            *(__half2*)yp        = __halves2half2(h0, h1);
            *(__half2*)(yp + C1) = __halves2half2(lo0, lo1);
        }
        {
            float v0 = o[i][2] * invl1, v1 = o[i][3] * invl1;
            __half h0, lo0, h1, lo1;
            split_f16(v0, h0, lo0); split_f16(v1, h1, lo1);
            __half* yp = ye + (rowg + 8) * (2L * C1) + colg;
            *(__half2*)yp        = __halves2half2(h0, h1);
            *(__half2*)(yp + C1) = __halves2half2(lo0, lo1);
        }
    }
}

// ---------------- launcher ----------------
extern "C" void kernel_launch(void* const* d_in, const int* in_sizes, int n_in,
                              void* d_out, int out_size)
{
    const float* x      = (const float*)d_in[0];
    const float* ln1_w  = (const float*)d_in[1];
    const float* ln1_b  = (const float*)d_in[2];
    const float* w_qkv  = (const float*)d_in[3];
    const float* b_qkv  = (const float*)d_in[4];
    const float* w_o    = (const float*)d_in[5];
    const float* b_o    = (const float*)d_in[6];
    const float* ln2_w  = (const float*)d_in[7];
    const float* ln2_b  = (const float*)d_in[8];
    const float* w_fc   = (const float*)d_in[9];
    const float* b_fc   = (const float*)d_in[10];
    const float* w_proj = (const float*)d_in[11];
    const float* b_proj = (const float*)d_in[12];
    float* out = (float*)d_out;

    float *qkv, *x1;
    __half *wqkv_t, *wo_t, *wfc_t, *wpr_t, *ln1e, *atte, *ln2e, *he;
    cudaGetSymbolAddress((void**)&qkv,   g_qkv);
    cudaGetSymbolAddress((void**)&x1,    g_x1);
    cudaGetSymbolAddress((void**)&wqkv_t, g_wqkv_t);
    cudaGetSymbolAddress((void**)&wo_t,   g_wo_t);
    cudaGetSymbolAddress((void**)&wfc_t,  g_wfc_t);
    cudaGetSymbolAddress((void**)&wpr_t,  g_wpr_t);
    cudaGetSymbolAddress((void**)&ln1e,   g_ln1e);
    cudaGetSymbolAddress((void**)&atte,   g_atte);
    cudaGetSymbolAddress((void**)&ln2e,   g_ln2e);
    cudaGetSymbolAddress((void**)&he,     g_he);

    cudaFuncSetAttribute(mma_gemm<0>, cudaFuncAttributeMaxDynamicSharedMemorySize, GEMM_SMEM_BYTES);
    cudaFuncSetAttribute(mma_gemm<1>, cudaFuncAttributeMaxDynamicSharedMemorySize, GEMM_SMEM_BYTES);
    cudaFuncSetAttribute(mma_gemm<2>, cudaFuncAttributeMaxDynamicSharedMemorySize, GEMM_SMEM_BYTES);

    // weight transpose + fp16 (Bt layouts, segments [hi, hi])
    conv_w_kernel<<<dim3(C3 / 32, C1 / 32), dim3(32, 8)>>>(w_qkv,  wqkv_t, C1, C3);
    conv_w_kernel<<<dim3(C1 / 32, C1 / 32), dim3(32, 8)>>>(w_o,    wo_t,   C1, C1);
    conv_w_kernel<<<dim3(C4 / 32, C1 / 32), dim3(32, 8)>>>(w_fc,   wfc_t,  C1, C4);
    conv_w_kernel<<<dim3(C1 / 32, C4 / 32), dim3(32, 8)>>>(w_proj, wpr_t,  C4, C1);

    // 1. LN1 -> ext
    ln_ext_kernel<<<BT, 256>>>(x, ln1_w, ln1_b, ln1e);
    // 2. QKV GEMM -> fp32 qkv
    mma_gemm<0><<<dim3(C3 / BN, BT / BM), NTH, GEMM_SMEM_BYTES>>>(ln1e, wqkv_t, b_qkv, nullptr, qkv, nullptr, C3, 2 * C1);
    // 3. attention -> ext
    attn_kernel<<<dim3(TT / 64, NH, BB), 128>>>(qkv, atte);
    // 4. O-proj + residual(x) -> fp32 x1
    mma_gemm<1><<<dim3(C1 / BN, BT / BM), NTH, GEMM_SMEM_BYTES>>>(atte, wo_t, b_o, x, x1, nullptr, C1, 2 * C1);
    // 5. LN2 -> ext
    ln_ext_kernel<<<BT, 256>>>(x1, ln2_w, ln2_b, ln2e);
    // 6. FC + GELU -> ext fp16 h
    mma_gemm<2><<<dim3(C4 / BN, BT / BM), NTH, GEMM_SMEM_BYTES>>>(ln2e, wfc_t, b_fc, nullptr, nullptr, he, C4, 2 * C1);
    // 7. down-proj + residual(x1) -> out
    mma_gemm<1><<<dim3(C1 / BN, BT / BM), NTH, GEMM_SMEM_BYTES>>>(he, wpr_t, b_proj, x1, out, nullptr, C1, 2 * C4);
}

// round 8
// speedup vs baseline: 7.4268x; 2.0379x over previous
#include <cuda_runtime.h>
#include <cuda_fp16.h>
#include <cstdint>

// ---------------- problem constants ----------------
#define BT   8192      // B*T
#define TT   1024      // T
#define BB   8         // B
#define C1   1024
#define C3   3072
#define C4   4096
#define NH   16
#define HD   64
#define LN_EPS 1e-5f

// GEMM tiling (mma.sync path)
#define BM   128
#define BN   128
#define BK   32
#define NTH  256
#define STAGES 3
#define ROWB 80                         // bytes per smem row (32 f16 + 8 pad)
#define STAGE_BYTES (2 * BM * ROWB)     // A tile + B tile = 20480
#define GEMM_SMEM_BYTES (STAGES * STAGE_BYTES)   // 61440

// ---------------- scratch (device globals; no allocation) ----------------
__device__ __align__(128) float  g_x1 [(size_t)BT * C1];
__device__ __align__(128) __half g_qkv[(size_t)BT * C3];
__device__ __align__(128) __half g_ln1[(size_t)BT * C1];
__device__ __align__(128) __half g_att[(size_t)BT * C1];
__device__ __align__(128) __half g_ln2[(size_t)BT * C1];
__device__ __align__(128) __half g_he [(size_t)BT * C4];
__device__ __align__(128) __half g_wqkv_t[(size_t)C3 * C1];
__device__ __align__(128) __half g_wo_t  [(size_t)C1 * C1];
__device__ __align__(128) __half g_wfc_t [(size_t)C4 * C1];
__device__ __align__(128) __half g_wpr_t [(size_t)C1 * C4];

// ---------------- helpers ----------------
__device__ __forceinline__ uint32_t smem_u32(const void* p) {
    uint32_t a;
    asm("{ .reg .u64 t; cvta.to.shared.u64 t, %1; cvt.u32.u64 %0, t; }" : "=r"(a) : "l"(p));
    return a;
}
__device__ __forceinline__ void cp_async16(uint32_t saddr, const void* g) {
    asm volatile("cp.async.cg.shared.global [%0], [%1], 16;" :: "r"(saddr), "l"(g));
}
#define CP_COMMIT() asm volatile("cp.async.commit_group;" ::: "memory")
#define CP_WAIT(n)  asm volatile("cp.async.wait_group %0;" :: "n"(n) : "memory")

__device__ __forceinline__ void ldsm_x4(uint32_t* r, uint32_t addr) {
    asm volatile("ldmatrix.sync.aligned.m8n8.x4.shared.b16 {%0,%1,%2,%3}, [%4];"
        : "=r"(r[0]), "=r"(r[1]), "=r"(r[2]), "=r"(r[3]) : "r"(addr));
}
__device__ __forceinline__ void ldsm_x4_t(uint32_t* r, uint32_t addr) {
    asm volatile("ldmatrix.sync.aligned.m8n8.x4.trans.shared.b16 {%0,%1,%2,%3}, [%4];"
        : "=r"(r[0]), "=r"(r[1]), "=r"(r[2]), "=r"(r[3]) : "r"(addr));
}
__device__ __forceinline__ void mma16816(float* c, const uint32_t* a, const uint32_t* b) {
    asm volatile("mma.sync.aligned.m16n8k16.row.col.f32.f16.f16.f32 "
        "{%0,%1,%2,%3}, {%4,%5,%6,%7}, {%8,%9}, {%0,%1,%2,%3};"
        : "+f"(c[0]), "+f"(c[1]), "+f"(c[2]), "+f"(c[3])
        : "r"(a[0]), "r"(a[1]), "r"(a[2]), "r"(a[3]), "r"(b[0]), "r"(b[1]));
}
__device__ __forceinline__ uint32_t pack_h2(float a, float b) {
    __half2 h = __floats2half2_rn(a, b);
    return *(uint32_t*)&h;
}

// ---------------- weight transpose -> fp16 ----------------
// W[K,N] fp32  ->  Wt[N,K] fp16
__global__ void conv_w_kernel(const float* __restrict__ W, __half* __restrict__ Wt, int K, int N)
{
    __shared__ float tile[32][33];
    const int k0 = blockIdx.y * 32, n0 = blockIdx.x * 32;
    const int tx = threadIdx.x, ty = threadIdx.y;   // 32 x 8
#pragma unroll
    for (int i = 0; i < 32; i += 8)
        tile[ty + i][tx] = W[(long)(k0 + ty + i) * N + n0 + tx];
    __syncthreads();
#pragma unroll
    for (int i = 0; i < 32; i += 8) {
        const int n = ty + i;
        Wt[(long)(n0 + n) * K + k0 + tx] = __float2half_rn(tile[tx][n]);
    }
}

// ---------------- LayerNorm -> fp16 [row, C1] -------------
__global__ void ln_f16_kernel(const float* __restrict__ x,
                              const float* __restrict__ w,
                              const float* __restrict__ b,
                              __half* __restrict__ y)
{
    const int row = blockIdx.x;
    const float4* xr = (const float4*)(x + (size_t)row * C1);
    float4 v = xr[threadIdx.x];
    float s  = v.x + v.y + v.z + v.w;
    float s2 = v.x*v.x + v.y*v.y + v.z*v.z + v.w*v.w;
    __shared__ float red[2][8];
    for (int off = 16; off > 0; off >>= 1) {
        s  += __shfl_down_sync(0xffffffffu, s,  off);
        s2 += __shfl_down_sync(0xffffffffu, s2, off);
    }
    int warp = threadIdx.x >> 5, lane = threadIdx.x & 31;
    if (lane == 0) { red[0][warp] = s; red[1][warp] = s2; }
    __syncthreads();
    float ts = 0.f, ts2 = 0.f;
#pragma unroll
    for (int i = 0; i < 8; i++) { ts += red[0][i]; ts2 += red[1][i]; }
    float mean = ts * (1.0f / C1);
    float var  = ts2 * (1.0f / C1) - mean * mean;
    float inv  = rsqrtf(var + LN_EPS);

    const float4 wv = ((const float4*)w)[threadIdx.x];
    const float4 bv = ((const float4*)b)[threadIdx.x];
    float o0 = (v.x - mean) * inv * wv.x + bv.x;
    float o1 = (v.y - mean) * inv * wv.y + bv.y;
    float o2 = (v.z - mean) * inv * wv.z + bv.z;
    float o3 = (v.w - mean) * inv * wv.w + bv.w;
    __half2* p = (__half2*)(y + (size_t)row * C1 + threadIdx.x * 4);
    p[0] = __floats2half2_rn(o0, o1);
    p[1] = __floats2half2_rn(o2, o3);
}

// ---------------- mma.sync GEMM: D = A[M,K] @ Bt[N,K]^T + bias ----------
// EPI: 0 = fp16 out + bias; 1 = fp32 out + bias + residual; 2 = gelu -> fp16 out
template<int EPI>
__global__ void __launch_bounds__(NTH)
mma_gemm(const __half* __restrict__ A,
         const __half* __restrict__ Bt,
         const float* __restrict__ bias,
         const float* __restrict__ res,
         float* __restrict__ Cf,
         __half* __restrict__ Ch,
         int N, int K)
{
    extern __shared__ char smem[];
    const uint32_t sbase = smem_u32(smem);
    const int tid  = threadIdx.x;
    const int wid  = tid >> 5, lane = tid & 31;
    const int wm   = (wid & 3) * 32;        // warp row base within tile
    const int wn   = (wid >> 2) * 64;       // warp col base within tile

    const long row0 = (long)blockIdx.y * BM;
    const long col0 = (long)blockIdx.x * BN;
    const __half* Ab = A  + row0 * K;
    const __half* Bb = Bt + col0 * K;

    const int NKB = K / BK;

    float acc[2][8][4];
#pragma unroll
    for (int mi = 0; mi < 2; mi++)
#pragma unroll
        for (int nj = 0; nj < 8; nj++)
#pragma unroll
            for (int q = 0; q < 4; q++) acc[mi][nj][q] = 0.f;

    const int grp = lane >> 3;
    const uint32_t a_off = (uint32_t)((wm + (grp & 1) * 8 + (lane & 7)) * ROWB + (grp >> 1) * 16);
    const uint32_t b_off = (uint32_t)(BM * ROWB + (wn + (grp >> 1) * 8 + (lane & 7)) * ROWB + (grp & 1) * 16);

    auto load_tile = [&](int buf, long k0) {
        const uint32_t abase = sbase + buf * STAGE_BYTES;
        const uint32_t bbase = abase + BM * ROWB;
#pragma unroll
        for (int t = 0; t < 2; t++) {
            int o = tid + t * NTH;          // 0..511
            int r = o >> 2, seg = o & 3;
            cp_async16(abase + r * ROWB + seg * 16, Ab + (long)r * K + k0 + seg * 8);
        }
#pragma unroll
        for (int t = 0; t < 2; t++) {
            int o = tid + t * NTH;
            int r = o >> 2, seg = o & 3;
            cp_async16(bbase + r * ROWB + seg * 16, Bb + (long)r * K + k0 + seg * 8);
        }
        CP_COMMIT();
    };

#pragma unroll
    for (int s = 0; s < STAGES - 1; s++) load_tile(s, (long)s * BK);

    for (int kb = 0; kb < NKB; kb++) {
        CP_WAIT(STAGES - 2);
        __syncthreads();

        const int buf = kb % STAGES;
        const uint32_t sbuf = sbase + buf * STAGE_BYTES;

#pragma unroll
        for (int ks = 0; ks < 2; ks++) {
            uint32_t afr[2][4];
#pragma unroll
            for (int mi = 0; mi < 2; mi++)
                ldsm_x4(afr[mi], sbuf + a_off + mi * 16 * ROWB + ks * 32);
            uint32_t bfr[8][2];
#pragma unroll
            for (int njp = 0; njp < 4; njp++) {
                uint32_t t[4];
                ldsm_x4(t, sbuf + b_off + njp * 16 * ROWB + ks * 32);
                bfr[2*njp][0] = t[0]; bfr[2*njp][1] = t[1];
                bfr[2*njp+1][0] = t[2]; bfr[2*njp+1][1] = t[3];
            }
#pragma unroll
            for (int mi = 0; mi < 2; mi++)
#pragma unroll
                for (int nj = 0; nj < 8; nj++)
                    mma16816(acc[mi][nj], afr[mi], bfr[nj]);
        }

        // safe without a trailing sync: buffer (kb+2)%3 was last read at kb-1,
        // ordered by the collective __syncthreads above.
        const int nk = kb + STAGES - 1;
        if (nk < NKB) load_tile(nk % STAGES, (long)nk * BK);
    }

    // ---- epilogue ----
#pragma unroll
    for (int mi = 0; mi < 2; mi++) {
#pragma unroll
        for (int rr = 0; rr < 2; rr++) {
            const long R = row0 + wm + mi * 16 + (lane >> 2) + rr * 8;
#pragma unroll
            for (int nj = 0; nj < 8; nj++) {
                const long CC = col0 + wn + nj * 8 + (lane & 3) * 2;
                float v0 = acc[mi][nj][rr * 2 + 0] + bias[CC];
                float v1 = acc[mi][nj][rr * 2 + 1] + bias[CC + 1];
                if (EPI == 0) {
                    *(__half2*)(Ch + R * N + CC) = __floats2half2_rn(v0, v1);
                } else if (EPI == 1) {
                    const float2 rv = *(const float2*)(res + R * N + CC);
                    *(float2*)(Cf + R * N + CC) = make_float2(v0 + rv.x, v1 + rv.y);
                } else {
                    float t0 = v0 + 0.044715f * v0 * v0 * v0;
                    float t1 = v1 + 0.044715f * v1 * v1 * v1;
                    v0 = v0 / (1.0f + __expf(-1.5957691216057308f * t0));
                    v1 = v1 / (1.0f + __expf(-1.5957691216057308f * t1));
                    *(__half2*)(Ch + R * N + CC) = __floats2half2_rn(v0, v1);
                }
            }
        }
    }
}

// ---------------- tensor-core causal flash attention (fp16 in/out) ------------
// grid (T/64, NH, B), 128 threads (4 warps x 16 q rows); 64-key tiles.
#define AROW 72   // halves per smem row (64 + 8 pad)
__global__ void __launch_bounds__(128)
attn_kernel(const __half* __restrict__ qkv, __half* __restrict__ y)
{
    const int qb = blockIdx.x, h = blockIdx.y, b = blockIdx.z;
    const int q0g = qb * 64;
    const __half* base = qkv + (size_t)b * TT * C3 + h * HD;

    __shared__ __half sq[64 * AROW];
    __shared__ __half sk[64 * AROW];
    __shared__ __half sv[64 * AROW];

    const int tid = threadIdx.x;
    const int wid = tid >> 5, lane = tid & 31;
    const int wq = wid * 16;
    const int grp = lane >> 3;

    const uint32_t sqb = smem_u32(sq), skb = smem_u32(sk), svb = smem_u32(sv);

    // load Q (64 x 64 fp16)
#pragma unroll
    for (int t = 0; t < 4; t++) {
        int i = tid + t * 128;              // 0..511
        int r = i >> 3, c8 = (i & 7) * 8;
        uint4 v = *(const uint4*)(base + (size_t)(q0g + r) * C3 + c8);
        *(uint4*)(sq + r * AROW + c8) = v;
    }
    __syncthreads();

    uint32_t qf[4][4];
    {
        const uint32_t qoff = (uint32_t)((wq + (grp & 1) * 8 + (lane & 7)) * AROW * 2 + (grp >> 1) * 16);
#pragma unroll
        for (int kd = 0; kd < 4; kd++)
            ldsm_x4(qf[kd], sqb + qoff + kd * 32);
    }

    float o[8][4];
#pragma unroll
    for (int i = 0; i < 8; i++)
#pragma unroll
        for (int q = 0; q < 4; q++) o[i][q] = 0.f;
    float m0 = -1e30f, m1 = -1e30f, l0 = 0.f, l1 = 0.f;

    const uint32_t kfoff = (uint32_t)(((grp >> 1) * 8 + (lane & 7)) * AROW * 2 + (grp & 1) * 16);
    const uint32_t vfoff = (uint32_t)(((grp & 1) * 8 + (lane & 7)) * AROW * 2 + (grp >> 1) * 16);

    for (int kt = 0; kt <= qb; kt++) {
        __syncthreads();
        // load K, V tiles (64 x 64 each, fp16)
#pragma unroll
        for (int t = 0; t < 4; t++) {
            int i = tid + t * 128;
            int r = i >> 3, c8 = (i & 7) * 8;
            const __half* kp = base + (size_t)(kt * 64 + r) * C3 + C1 + c8;
            *(uint4*)(sk + r * AROW + c8) = *(const uint4*)kp;
            *(uint4*)(sv + r * AROW + c8) = *(const uint4*)(kp + C1);
        }
        __syncthreads();

        // S = Q K^T : 16 x 64 per warp
        float c[8][4];
#pragma unroll
        for (int nj = 0; nj < 8; nj++)
#pragma unroll
            for (int q = 0; q < 4; q++) c[nj][q] = 0.f;
#pragma unroll
        for (int kd = 0; kd < 4; kd++) {
#pragma unroll
            for (int njp = 0; njp < 4; njp++) {
                uint32_t t[4];
                ldsm_x4(t, skb + kfoff + njp * 16 * AROW * 2 + kd * 32);
                uint32_t bA[2] = {t[0], t[1]}, bB[2] = {t[2], t[3]};
                mma16816(c[2*njp],   qf[kd], bA);
                mma16816(c[2*njp+1], qf[kd], bB);
            }
        }

        // scale + causal mask
        const int ra = q0g + wq + (lane >> 2);
        if (kt == qb) {
#pragma unroll
            for (int nj = 0; nj < 8; nj++) {
                const int cb = kt * 64 + nj * 8 + (lane & 3) * 2;
#pragma unroll
                for (int e = 0; e < 2; e++) {
                    c[nj][e]     = (cb + e > ra)     ? -1e30f : c[nj][e] * 0.125f;
                    c[nj][2 + e] = (cb + e > ra + 8) ? -1e30f : c[nj][2 + e] * 0.125f;
                }
            }
        } else {
#pragma unroll
            for (int nj = 0; nj < 8; nj++)
#pragma unroll
                for (int q = 0; q < 4; q++) c[nj][q] *= 0.125f;
        }

        // online softmax
        float mxa = -1e30f, mxb = -1e30f;
#pragma unroll
        for (int nj = 0; nj < 8; nj++) {
            mxa = fmaxf(mxa, fmaxf(c[nj][0], c[nj][1]));
            mxb = fmaxf(mxb, fmaxf(c[nj][2], c[nj][3]));
        }
        mxa = fmaxf(mxa, __shfl_xor_sync(0xffffffffu, mxa, 1));
        mxa = fmaxf(mxa, __shfl_xor_sync(0xffffffffu, mxa, 2));
        mxb = fmaxf(mxb, __shfl_xor_sync(0xffffffffu, mxb, 1));
        mxb = fmaxf(mxb, __shfl_xor_sync(0xffffffffu, mxb, 2));
        const float mna = fmaxf(m0, mxa), mnb = fmaxf(m1, mxb);
        const float alpha_a = __expf(m0 - mna), alpha_b = __expf(m1 - mnb);
        m0 = mna; m1 = mnb;
        float suma = 0.f, sumb = 0.f;
#pragma unroll
        for (int nj = 0; nj < 8; nj++) {
            c[nj][0] = __expf(c[nj][0] - mna);
            c[nj][1] = __expf(c[nj][1] - mna);
            c[nj][2] = __expf(c[nj][2] - mnb);
            c[nj][3] = __expf(c[nj][3] - mnb);
            suma += c[nj][0] + c[nj][1];
            sumb += c[nj][2] + c[nj][3];
        }
        suma += __shfl_xor_sync(0xffffffffu, suma, 1);
        suma += __shfl_xor_sync(0xffffffffu, suma, 2);
        sumb += __shfl_xor_sync(0xffffffffu, sumb, 1);
        sumb += __shfl_xor_sync(0xffffffffu, sumb, 2);
        l0 = l0 * alpha_a + suma;
        l1 = l1 * alpha_b + sumb;
#pragma unroll
        for (int i = 0; i < 8; i++) {
            o[i][0] *= alpha_a; o[i][1] *= alpha_a;
            o[i][2] *= alpha_b; o[i][3] *= alpha_b;
        }

        // P fragments
        uint32_t pf[4][4];
#pragma unroll
        for (int ks = 0; ks < 4; ks++) {
            pf[ks][0] = pack_h2(c[2*ks][0],   c[2*ks][1]);
            pf[ks][1] = pack_h2(c[2*ks][2],   c[2*ks][3]);
            pf[ks][2] = pack_h2(c[2*ks+1][0], c[2*ks+1][1]);
            pf[ks][3] = pack_h2(c[2*ks+1][2], c[2*ks+1][3]);
        }

        // O += P @ V
#pragma unroll
        for (int ks = 0; ks < 4; ks++) {
#pragma unroll
            for (int dp = 0; dp < 4; dp++) {
                uint32_t t[4];
                ldsm_x4_t(t, svb + vfoff + ks * 16 * AROW * 2 + dp * 32);
                uint32_t bA[2] = {t[0], t[1]}, bB[2] = {t[2], t[3]};
                mma16816(o[2*dp],   pf[ks], bA);
                mma16816(o[2*dp+1], pf[ks], bB);
            }
        }
    }

    // epilogue: divide by l, plain fp16 out [BT, C1]
    const float invl0 = 1.0f / l0, invl1 = 1.0f / l1;
    const long rowg = (long)b * TT + q0g + wq + (lane >> 2);
#pragma unroll
    for (int i = 0; i < 8; i++) {
        const int colg = h * HD + i * 8 + (lane & 3) * 2;
        *(__half2*)(y + rowg * C1 + colg)       = __floats2half2_rn(o[i][0] * invl0, o[i][1] * invl0);
        *(__half2*)(y + (rowg + 8) * C1 + colg) = __floats2half2_rn(o[i][2] * invl1, o[i][3] * invl1);
    }
}

// ---------------- launcher ----------------
extern "C" void kernel_launch(void* const* d_in, const int* in_sizes, int n_in,
                              void* d_out, int out_size)
{
    const float* x      = (const float*)d_in[0];
    const float* ln1_w  = (const float*)d_in[1];
    const float* ln1_b  = (const float*)d_in[2];
    const float* w_qkv  = (const float*)d_in[3];
    const float* b_qkv  = (const float*)d_in[4];
    const float* w_o    = (const float*)d_in[5];
    const float* b_o    = (const float*)d_in[6];
    const float* ln2_w  = (const float*)d_in[7];
    const float* ln2_b  = (const float*)d_in[8];
    const float* w_fc   = (const float*)d_in[9];
    const float* b_fc   = (const float*)d_in[10];
    const float* w_proj = (const float*)d_in[11];
    const float* b_proj = (const float*)d_in[12];
    float* out = (float*)d_out;

    float* x1;
    __half *qkv, *ln1, *att, *ln2, *he, *wqkv_t, *wo_t, *wfc_t, *wpr_t;
    cudaGetSymbolAddress((void**)&x1,   g_x1);
    cudaGetSymbolAddress((void**)&qkv,  g_qkv);
    cudaGetSymbolAddress((void**)&ln1,  g_ln1);
    cudaGetSymbolAddress((void**)&att,  g_att);
    cudaGetSymbolAddress((void**)&ln2,  g_ln2);
    cudaGetSymbolAddress((void**)&he,   g_he);
    cudaGetSymbolAddress((void**)&wqkv_t, g_wqkv_t);
    cudaGetSymbolAddress((void**)&wo_t,   g_wo_t);
    cudaGetSymbolAddress((void**)&wfc_t,  g_wfc_t);
    cudaGetSymbolAddress((void**)&wpr_t,  g_wpr_t);

    cudaFuncSetAttribute(mma_gemm<0>, cudaFuncAttributeMaxDynamicSharedMemorySize, GEMM_SMEM_BYTES);
    cudaFuncSetAttribute(mma_gemm<1>, cudaFuncAttributeMaxDynamicSharedMemorySize, GEMM_SMEM_BYTES);
    cudaFuncSetAttribute(mma_gemm<2>, cudaFuncAttributeMaxDynamicSharedMemorySize, GEMM_SMEM_BYTES);

    // weight transpose -> fp16 [N,K]
    conv_w_kernel<<<dim3(C3 / 32, C1 / 32), dim3(32, 8)>>>(w_qkv,  wqkv_t, C1, C3);
    conv_w_kernel<<<dim3(C1 / 32, C1 / 32), dim3(32, 8)>>>(w_o,    wo_t,   C1, C1);
    conv_w_kernel<<<dim3(C4 / 32, C1 / 32), dim3(32, 8)>>>(w_fc,   wfc_t,  C1, C4);
    conv_w_kernel<<<dim3(C1 / 32, C4 / 32), dim3(32, 8)>>>(w_proj, wpr_t,  C4, C1);

    // 1. LN1 -> fp16
    ln_f16_kernel<<<BT, 256>>>(x, ln1_w, ln1_b, ln1);
    // 2. QKV GEMM -> fp16 qkv
    mma_gemm<0><<<dim3(C3 / BN, BT / BM), NTH, GEMM_SMEM_BYTES>>>(ln1, wqkv_t, b_qkv, nullptr, nullptr, qkv, C3, C1);
    // 3. attention -> fp16 att
    attn_kernel<<<dim3(TT / 64, NH, BB), 128>>>(qkv, att);
    // 4. O-proj + residual(x) -> fp32 x1
    mma_gemm<1><<<dim3(C1 / BN, BT / BM), NTH, GEMM_SMEM_BYTES>>>(att, wo_t, b_o, x, x1, nullptr, C1, C1);
    // 5. LN2 -> fp16
    ln_f16_kernel<<<BT, 256>>>(x1, ln2_w, ln2_b, ln2);
    // 6. FC + GELU -> fp16 h
    mma_gemm<2><<<dim3(C4 / BN, BT / BM), NTH, GEMM_SMEM_BYTES>>>(ln2, wfc_t, b_fc, nullptr, nullptr, he, C4, C1);
    // 7. down-proj + residual(x1) -> out (fp32)
    mma_gemm<1><<<dim3(C1 / BN, BT / BM), NTH, GEMM_SMEM_BYTES>>>(he, wpr_t, b_proj, x1, out, nullptr, C1, C4);
}

// round 9
// speedup vs baseline: 7.6185x; 1.0258x over previous
#include <cuda_runtime.h>
#include <cuda_fp16.h>
#include <cstdint>

// ---------------- problem constants ----------------
#define BT   8192      // B*T
#define TT   1024      // T
#define BB   8         // B
#define C1   1024
#define C3   3072
#define C4   4096
#define NH   16
#define HD   64
#define LN_EPS 1e-5f

// GEMM tiling (mma.sync path)
#define BM   128
#define BN   128
#define BK   32
#define NTH  256
#define STAGES 3
#define ROWB 80                         // bytes per smem row (32 f16 + 8 pad)
#define STAGE_BYTES (2 * BM * ROWB)     // A tile + B tile = 20480
#define GEMM_SMEM_BYTES (STAGES * STAGE_BYTES)   // 61440

// ---------------- scratch (device globals; no allocation) ----------------
__device__ __align__(128) float  g_x1 [(size_t)BT * C1];
__device__ __align__(128) __half g_qkv[(size_t)BT * C3];
__device__ __align__(128) __half g_ln1[(size_t)BT * C1];
__device__ __align__(128) __half g_att[(size_t)BT * C1];
__device__ __align__(128) __half g_ln2[(size_t)BT * C1];
__device__ __align__(128) __half g_he [(size_t)BT * C4];
__device__ __align__(128) __half g_wqkv_t[(size_t)C3 * C1];
__device__ __align__(128) __half g_wo_t  [(size_t)C1 * C1];
__device__ __align__(128) __half g_wfc_t [(size_t)C4 * C1];
__device__ __align__(128) __half g_wpr_t [(size_t)C1 * C4];

// ---------------- helpers ----------------
__device__ __forceinline__ uint32_t smem_u32(const void* p) {
    uint32_t a;
    asm("{ .reg .u64 t; cvta.to.shared.u64 t, %1; cvt.u32.u64 %0, t; }" : "=r"(a) : "l"(p));
    return a;
}
__device__ __forceinline__ void cp_async16(uint32_t saddr, const void* g) {
    asm volatile("cp.async.cg.shared.global [%0], [%1], 16;" :: "r"(saddr), "l"(g));
}
#define CP_COMMIT() asm volatile("cp.async.commit_group;" ::: "memory")
#define CP_WAIT(n)  asm volatile("cp.async.wait_group %0;" :: "n"(n) : "memory")

__device__ __forceinline__ void ldsm_x4(uint32_t* r, uint32_t addr) {
    asm volatile("ldmatrix.sync.aligned.m8n8.x4.shared.b16 {%0,%1,%2,%3}, [%4];"
        : "=r"(r[0]), "=r"(r[1]), "=r"(r[2]), "=r"(r[3]) : "r"(addr));
}
__device__ __forceinline__ void ldsm_x4_t(uint32_t* r, uint32_t addr) {
    asm volatile("ldmatrix.sync.aligned.m8n8.x4.trans.shared.b16 {%0,%1,%2,%3}, [%4];"
        : "=r"(r[0]), "=r"(r[1]), "=r"(r[2]), "=r"(r[3]) : "r"(addr));
}
__device__ __forceinline__ void mma16816(float* c, const uint32_t* a, const uint32_t* b) {
    asm volatile("mma.sync.aligned.m16n8k16.row.col.f32.f16.f16.f32 "
        "{%0,%1,%2,%3}, {%4,%5,%6,%7}, {%8,%9}, {%0,%1,%2,%3};"
        : "+f"(c[0]), "+f"(c[1]), "+f"(c[2]), "+f"(c[3])
        : "r"(a[0]), "r"(a[1]), "r"(a[2]), "r"(a[3]), "r"(b[0]), "r"(b[1]));
}
__device__ __forceinline__ uint32_t pack_h2(float a, float b) {
    __half2 h = __floats2half2_rn(a, b);
    return *(uint32_t*)&h;
}

// ---------------- weight transpose -> fp16 ----------------
// W[K,N] fp32  ->  Wt[N,K] fp16
__global__ void conv_w_kernel(const float* __restrict__ W, __half* __restrict__ Wt, int K, int N)
{
    __shared__ float tile[32][33];
    const int k0 = blockIdx.y * 32, n0 = blockIdx.x * 32;
    const int tx = threadIdx.x, ty = threadIdx.y;   // 32 x 8
#pragma unroll
    for (int i = 0; i < 32; i += 8)
        tile[ty + i][tx] = W[(long)(k0 + ty + i) * N + n0 + tx];
    __syncthreads();
#pragma unroll
    for (int i = 0; i < 32; i += 8) {
        const int n = ty + i;
        Wt[(long)(n0 + n) * K + k0 + tx] = __float2half_rn(tile[tx][n]);
    }
}

// ---------------- LayerNorm -> fp16 [row, C1] -------------
__global__ void ln_f16_kernel(const float* __restrict__ x,
                              const float* __restrict__ w,
                              const float* __restrict__ b,
                              __half* __restrict__ y)
{
    const int row = blockIdx.x;
    const float4* xr = (const float4*)(x + (size_t)row * C1);
    float4 v = xr[threadIdx.x];
    float s  = v.x + v.y + v.z + v.w;
    float s2 = v.x*v.x + v.y*v.y + v.z*v.z + v.w*v.w;
    __shared__ float red[2][8];
    for (int off = 16; off > 0; off >>= 1) {
        s  += __shfl_down_sync(0xffffffffu, s,  off);
        s2 += __shfl_down_sync(0xffffffffu, s2, off);
    }
    int warp = threadIdx.x >> 5, lane = threadIdx.x & 31;
    if (lane == 0) { red[0][warp] = s; red[1][warp] = s2; }
    __syncthreads();
    float ts = 0.f, ts2 = 0.f;
#pragma unroll
    for (int i = 0; i < 8; i++) { ts += red[0][i]; ts2 += red[1][i]; }
    float mean = ts * (1.0f / C1);
    float var  = ts2 * (1.0f / C1) - mean * mean;
    float inv  = rsqrtf(var + LN_EPS);

    const float4 wv = ((const float4*)w)[threadIdx.x];
    const float4 bv = ((const float4*)b)[threadIdx.x];
    float o0 = (v.x - mean) * inv * wv.x + bv.x;
    float o1 = (v.y - mean) * inv * wv.y + bv.y;
    float o2 = (v.z - mean) * inv * wv.z + bv.z;
    float o3 = (v.w - mean) * inv * wv.w + bv.w;
    __half2* p = (__half2*)(y + (size_t)row * C1 + threadIdx.x * 4);
    p[0] = __floats2half2_rn(o0, o1);
    p[1] = __floats2half2_rn(o2, o3);
}

// ---------------- mma.sync GEMM: D = A[M,K] @ Bt[N,K]^T + bias ----------
// EPI: 0 = fp16 out + bias; 1 = fp32 out + bias + residual; 2 = gelu -> fp16 out
template<int EPI>
__global__ void __launch_bounds__(NTH, 2)
mma_gemm(const __half* __restrict__ A,
         const __half* __restrict__ Bt,
         const float* __restrict__ bias,
         const float* __restrict__ res,
         float* __restrict__ Cf,
         __half* __restrict__ Ch,
         int N, int K)
{
    extern __shared__ char smem[];
    const uint32_t sbase = smem_u32(smem);
    const int tid  = threadIdx.x;
    const int wid  = tid >> 5, lane = tid & 31;
    const int wm   = (wid & 3) * 32;        // warp row base within tile
    const int wn   = (wid >> 2) * 64;       // warp col base within tile

    const long row0 = (long)blockIdx.y * BM;
    const long col0 = (long)blockIdx.x * BN;
    const __half* Ab = A  + row0 * K;
    const __half* Bb = Bt + col0 * K;

    const int NKB = K / BK;

    float acc[2][8][4];
#pragma unroll
    for (int mi = 0; mi < 2; mi++)
#pragma unroll
        for (int nj = 0; nj < 8; nj++)
#pragma unroll
            for (int q = 0; q < 4; q++) acc[mi][nj][q] = 0.f;

    const int grp = lane >> 3;
    const uint32_t a_off = (uint32_t)((wm + (grp & 1) * 8 + (lane & 7)) * ROWB + (grp >> 1) * 16);
    const uint32_t b_off = (uint32_t)(BM * ROWB + (wn + (grp >> 1) * 8 + (lane & 7)) * ROWB + (grp & 1) * 16);

    auto load_tile = [&](int buf, long k0) {
        const uint32_t abase = sbase + buf * STAGE_BYTES;
        const uint32_t bbase = abase + BM * ROWB;
#pragma unroll
        for (int t = 0; t < 2; t++) {
            int o = tid + t * NTH;          // 0..511
            int r = o >> 2, seg = o & 3;
            cp_async16(abase + r * ROWB + seg * 16, Ab + (long)r * K + k0 + seg * 8);
        }
#pragma unroll
        for (int t = 0; t < 2; t++) {
            int o = tid + t * NTH;
            int r = o >> 2, seg = o & 3;
            cp_async16(bbase + r * ROWB + seg * 16, Bb + (long)r * K + k0 + seg * 8);
        }
        CP_COMMIT();
    };

#pragma unroll
    for (int s = 0; s < STAGES - 1; s++) load_tile(s, (long)s * BK);

    for (int kb = 0; kb < NKB; kb++) {
        CP_WAIT(STAGES - 2);
        __syncthreads();

        const int buf = kb % STAGES;
        const uint32_t sbuf = sbase + buf * STAGE_BYTES;

#pragma unroll
        for (int ks = 0; ks < 2; ks++) {
            uint32_t afr[2][4];
#pragma unroll
            for (int mi = 0; mi < 2; mi++)
                ldsm_x4(afr[mi], sbuf + a_off + mi * 16 * ROWB + ks * 32);
            uint32_t bfr[8][2];
#pragma unroll
            for (int njp = 0; njp < 4; njp++) {
                uint32_t t[4];
                ldsm_x4(t, sbuf + b_off + njp * 16 * ROWB + ks * 32);
                bfr[2*njp][0] = t[0]; bfr[2*njp][1] = t[1];
                bfr[2*njp+1][0] = t[2]; bfr[2*njp+1][1] = t[3];
            }
#pragma unroll
            for (int mi = 0; mi < 2; mi++)
#pragma unroll
                for (int nj = 0; nj < 8; nj++)
                    mma16816(acc[mi][nj], afr[mi], bfr[nj]);
        }

        // safe without a trailing sync: buffer (kb+2)%3 was last read at kb-1,
        // ordered by the collective __syncthreads above.
        const int nk = kb + STAGES - 1;
        if (nk < NKB) load_tile(nk % STAGES, (long)nk * BK);
    }

    // ---- epilogue ----
#pragma unroll
    for (int mi = 0; mi < 2; mi++) {
#pragma unroll
        for (int rr = 0; rr < 2; rr++) {
            const long R = row0 + wm + mi * 16 + (lane >> 2) + rr * 8;
#pragma unroll
            for (int nj = 0; nj < 8; nj++) {
                const long CC = col0 + wn + nj * 8 + (lane & 3) * 2;
                float v0 = acc[mi][nj][rr * 2 + 0] + bias[CC];
                float v1 = acc[mi][nj][rr * 2 + 1] + bias[CC + 1];
                if (EPI == 0) {
                    *(__half2*)(Ch + R * N + CC) = __floats2half2_rn(v0, v1);
                } else if (EPI == 1) {
                    const float2 rv = *(const float2*)(res + R * N + CC);
                    *(float2*)(Cf + R * N + CC) = make_float2(v0 + rv.x, v1 + rv.y);
                } else {
                    float t0 = v0 + 0.044715f * v0 * v0 * v0;
                    float t1 = v1 + 0.044715f * v1 * v1 * v1;
                    v0 = v0 / (1.0f + __expf(-1.5957691216057308f * t0));
                    v1 = v1 / (1.0f + __expf(-1.5957691216057308f * t1));
                    *(__half2*)(Ch + R * N + CC) = __floats2half2_rn(v0, v1);
                }
            }
        }
    }
}

// ---------------- tensor-core causal flash attention (fp16 in/out) ------------
// grid (T/64, NH, B), 128 threads (4 warps x 16 q rows); 64-key tiles.
#define AROW 72   // halves per smem row (64 + 8 pad)
__global__ void __launch_bounds__(128)
attn_kernel(const __half* __restrict__ qkv, __half* __restrict__ y)
{
    const int qb = blockIdx.x, h = blockIdx.y, b = blockIdx.z;
    const int q0g = qb * 64;
    const __half* base = qkv + (size_t)b * TT * C3 + h * HD;

    __shared__ __half sq[64 * AROW];
    __shared__ __half sk[64 * AROW];
    __shared__ __half sv[64 * AROW];

    const int tid = threadIdx.x;
    const int wid = tid >> 5, lane = tid & 31;
    const int wq = wid * 16;
    const int grp = lane >> 3;

    const uint32_t sqb = smem_u32(sq), skb = smem_u32(sk), svb = smem_u32(sv);

    // load Q (64 x 64 fp16)
#pragma unroll
    for (int t = 0; t < 4; t++) {
        int i = tid + t * 128;              // 0..511
        int r = i >> 3, c8 = (i & 7) * 8;
        uint4 v = *(const uint4*)(base + (size_t)(q0g + r) * C3 + c8);
        *(uint4*)(sq + r * AROW + c8) = v;
    }
    __syncthreads();

    uint32_t qf[4][4];
    {
        const uint32_t qoff = (uint32_t)((wq + (grp & 1) * 8 + (lane & 7)) * AROW * 2 + (grp >> 1) * 16);
#pragma unroll
        for (int kd = 0; kd < 4; kd++)
            ldsm_x4(qf[kd], sqb + qoff + kd * 32);
    }

    float o[8][4];
#pragma unroll
    for (int i = 0; i < 8; i++)
#pragma unroll
        for (int q = 0; q < 4; q++) o[i][q] = 0.f;
    float m0 = -1e30f, m1 = -1e30f, l0 = 0.f, l1 = 0.f;

    const uint32_t kfoff = (uint32_t)(((grp >> 1) * 8 + (lane & 7)) * AROW * 2 + (grp & 1) * 16);
    const uint32_t vfoff = (uint32_t)(((grp & 1) * 8 + (lane & 7)) * AROW * 2 + (grp >> 1) * 16);

    for (int kt = 0; kt <= qb; kt++) {
        __syncthreads();
        // load K, V tiles (64 x 64 each, fp16)
#pragma unroll
        for (int t = 0; t < 4; t++) {
            int i = tid + t * 128;
            int r = i >> 3, c8 = (i & 7) * 8;
            const __half* kp = base + (size_t)(kt * 64 + r) * C3 + C1 + c8;
            *(uint4*)(sk + r * AROW + c8) = *(const uint4*)kp;
            *(uint4*)(sv + r * AROW + c8) = *(const uint4*)(kp + C1);
        }
        __syncthreads();

        // S = Q K^T : 16 x 64 per warp
        float c[8][4];
#pragma unroll
        for (int nj = 0; nj < 8; nj++)
#pragma unroll
            for (int q = 0; q < 4; q++) c[nj][q] = 0.f;
#pragma unroll
        for (int kd = 0; kd < 4; kd++) {
#pragma unroll
            for (int njp = 0; njp < 4; njp++) {
                uint32_t t[4];
                ldsm_x4(t, skb + kfoff + njp * 16 * AROW * 2 + kd * 32);
                uint32_t bA[2] = {t[0], t[1]}, bB[2] = {t[2], t[3]};
                mma16816(c[2*njp],   qf[kd], bA);
                mma16816(c[2*njp+1], qf[kd], bB);
            }
        }

        // scale + causal mask
        const int ra = q0g + wq + (lane >> 2);
        if (kt == qb) {
#pragma unroll
            for (int nj = 0; nj < 8; nj++) {
                const int cb = kt * 64 + nj * 8 + (lane & 3) * 2;
#pragma unroll
                for (int e = 0; e < 2; e++) {
                    c[nj][e]     = (cb + e > ra)     ? -1e30f : c[nj][e] * 0.125f;
                    c[nj][2 + e] = (cb + e > ra + 8) ? -1e30f : c[nj][2 + e] * 0.125f;
                }
            }
        } else {
#pragma unroll
            for (int nj = 0; nj < 8; nj++)
#pragma unroll
                for (int q = 0; q < 4; q++) c[nj][q] *= 0.125f;
        }

        // online softmax
        float mxa = -1e30f, mxb = -1e30f;
#pragma unroll
        for (int nj = 0; nj < 8; nj++) {
            mxa = fmaxf(mxa, fmaxf(c[nj][0], c[nj][1]));
            mxb = fmaxf(mxb, fmaxf(c[nj][2], c[nj][3]));
        }
        mxa = fmaxf(mxa, __shfl_xor_sync(0xffffffffu, mxa, 1));
        mxa = fmaxf(mxa, __shfl_xor_sync(0xffffffffu, mxa, 2));
        mxb = fmaxf(mxb, __shfl_xor_sync(0xffffffffu, mxb, 1));
        mxb = fmaxf(mxb, __shfl_xor_sync(0xffffffffu, mxb, 2));
        const float mna = fmaxf(m0, mxa), mnb = fmaxf(m1, mxb);
        const float alpha_a = __expf(m0 - mna), alpha_b = __expf(m1 - mnb);
        m0 = mna; m1 = mnb;
        float suma = 0.f, sumb = 0.f;
#pragma unroll
        for (int nj = 0; nj < 8; nj++) {
            c[nj][0] = __expf(c[nj][0] - mna);
            c[nj][1] = __expf(c[nj][1] - mna);
            c[nj][2] = __expf(c[nj][2] - mnb);
            c[nj][3] = __expf(c[nj][3] - mnb);
            suma += c[nj][0] + c[nj][1];
            sumb += c[nj][2] + c[nj][3];
        }
        suma += __shfl_xor_sync(0xffffffffu, suma, 1);
        suma += __shfl_xor_sync(0xffffffffu, suma, 2);
        sumb += __shfl_xor_sync(0xffffffffu, sumb, 1);
        sumb += __shfl_xor_sync(0xffffffffu, sumb, 2);
        l0 = l0 * alpha_a + suma;
        l1 = l1 * alpha_b + sumb;
#pragma unroll
        for (int i = 0; i < 8; i++) {
            o[i][0] *= alpha_a; o[i][1] *= alpha_a;
            o[i][2] *= alpha_b; o[i][3] *= alpha_b;
        }

        // P fragments
        uint32_t pf[4][4];
#pragma unroll
        for (int ks = 0; ks < 4; ks++) {
            pf[ks][0] = pack_h2(c[2*ks][0],   c[2*ks][1]);
            pf[ks][1] = pack_h2(c[2*ks][2],   c[2*ks][3]);
            pf[ks][2] = pack_h2(c[2*ks+1][0], c[2*ks+1][1]);
            pf[ks][3] = pack_h2(c[2*ks+1][2], c[2*ks+1][3]);
        }

        // O += P @ V
#pragma unroll
        for (int ks = 0; ks < 4; ks++) {
#pragma unroll
            for (int dp = 0; dp < 4; dp++) {
                uint32_t t[4];
                ldsm_x4_t(t, svb + vfoff + ks * 16 * AROW * 2 + dp * 32);
                uint32_t bA[2] = {t[0], t[1]}, bB[2] = {t[2], t[3]};
                mma16816(o[2*dp],   pf[ks], bA);
                mma16816(o[2*dp+1], pf[ks], bB);
            }
        }
    }

    // epilogue: divide by l, plain fp16 out [BT, C1]
    const float invl0 = 1.0f / l0, invl1 = 1.0f / l1;
    const long rowg = (long)b * TT + q0g + wq + (lane >> 2);
#pragma unroll
    for (int i = 0; i < 8; i++) {
        const int colg = h * HD + i * 8 + (lane & 3) * 2;
        *(__half2*)(y + rowg * C1 + colg)       = __floats2half2_rn(o[i][0] * invl0, o[i][1] * invl0);
        *(__half2*)(y + (rowg + 8) * C1 + colg) = __floats2half2_rn(o[i][2] * invl1, o[i][3] * invl1);
    }
}

// ---------------- launcher ----------------
extern "C" void kernel_launch(void* const* d_in, const int* in_sizes, int n_in,
                              void* d_out, int out_size)
{
    const float* x      = (const float*)d_in[0];
    const float* ln1_w  = (const float*)d_in[1];
    const float* ln1_b  = (const float*)d_in[2];
    const float* w_qkv  = (const float*)d_in[3];
    const float* b_qkv  = (const float*)d_in[4];
    const float* w_o    = (const float*)d_in[5];
    const float* b_o    = (const float*)d_in[6];
    const float* ln2_w  = (const float*)d_in[7];
    const float* ln2_b  = (const float*)d_in[8];
    const float* w_fc   = (const float*)d_in[9];
    const float* b_fc   = (const float*)d_in[10];
    const float* w_proj = (const float*)d_in[11];
    const float* b_proj = (const float*)d_in[12];
    float* out = (float*)d_out;

    float* x1;
    __half *qkv, *ln1, *att, *ln2, *he, *wqkv_t, *wo_t, *wfc_t, *wpr_t;
    cudaGetSymbolAddress((void**)&x1,   g_x1);
    cudaGetSymbolAddress((void**)&qkv,  g_qkv);
    cudaGetSymbolAddress((void**)&ln1,  g_ln1);
    cudaGetSymbolAddress((void**)&att,  g_att);
    cudaGetSymbolAddress((void**)&ln2,  g_ln2);
    cudaGetSymbolAddress((void**)&he,   g_he);
    cudaGetSymbolAddress((void**)&wqkv_t, g_wqkv_t);
    cudaGetSymbolAddress((void**)&wo_t,   g_wo_t);
    cudaGetSymbolAddress((void**)&wfc_t,  g_wfc_t);
    cudaGetSymbolAddress((void**)&wpr_t,  g_wpr_t);

    cudaFuncSetAttribute(mma_gemm<0>, cudaFuncAttributeMaxDynamicSharedMemorySize, GEMM_SMEM_BYTES);
    cudaFuncSetAttribute(mma_gemm<1>, cudaFuncAttributeMaxDynamicSharedMemorySize, GEMM_SMEM_BYTES);
    cudaFuncSetAttribute(mma_gemm<2>, cudaFuncAttributeMaxDynamicSharedMemorySize, GEMM_SMEM_BYTES);

    // launch order arranged so ncu (-s 5 -c 1) profiles the QKV GEMM (launch #5)
    // 0. LN1 -> fp16 (depends only on x)
    ln_f16_kernel<<<BT, 256>>>(x, ln1_w, ln1_b, ln1);
    // 1-4. weight transpose -> fp16 [N,K]
    conv_w_kernel<<<dim3(C3 / 32, C1 / 32), dim3(32, 8)>>>(w_qkv,  wqkv_t, C1, C3);
    conv_w_kernel<<<dim3(C1 / 32, C1 / 32), dim3(32, 8)>>>(w_o,    wo_t,   C1, C1);
    conv_w_kernel<<<dim3(C4 / 32, C1 / 32), dim3(32, 8)>>>(w_fc,   wfc_t,  C1, C4);
    conv_w_kernel<<<dim3(C1 / 32, C4 / 32), dim3(32, 8)>>>(w_proj, wpr_t,  C4, C1);
    // 5. QKV GEMM -> fp16 qkv
    mma_gemm<0><<<dim3(C3 / BN, BT / BM), NTH, GEMM_SMEM_BYTES>>>(ln1, wqkv_t, b_qkv, nullptr, nullptr, qkv, C3, C1);
    // 6. attention -> fp16 att
    attn_kernel<<<dim3(TT / 64, NH, BB), 128>>>(qkv, att);
    // 7. O-proj + residual(x) -> fp32 x1
    mma_gemm<1><<<dim3(C1 / BN, BT / BM), NTH, GEMM_SMEM_BYTES>>>(att, wo_t, b_o, x, x1, nullptr, C1, C1);
    // 8. LN2 -> fp16
    ln_f16_kernel<<<BT, 256>>>(x1, ln2_w, ln2_b, ln2);
    // 9. FC + GELU -> fp16 h
    mma_gemm<2><<<dim3(C4 / BN, BT / BM), NTH, GEMM_SMEM_BYTES>>>(ln2, wfc_t, b_fc, nullptr, nullptr, he, C4, C1);
    // 10. down-proj + residual(x1) -> out (fp32)
    mma_gemm<1><<<dim3(C1 / BN, BT / BM), NTH, GEMM_SMEM_BYTES>>>(he, wpr_t, b_proj, x1, out, nullptr, C1, C4);
}

// round 10
// speedup vs baseline: 8.1569x; 1.0707x over previous
#include <cuda_runtime.h>
#include <cuda_fp16.h>
#include <cstdint>

// ---------------- problem constants ----------------
#define BT   8192      // B*T
#define TT   1024      // T
#define BB   8         // B
#define C1   1024
#define C3   3072
#define C4   4096
#define NH   16
#define HD   64
#define LN_EPS 1e-5f

// GEMM tiling (mma.sync path)
#define BM   128
#define BN   128
#define BK   64
#define NTH  256
#define STAGES 3
#define ROWB 144                        // bytes per smem row (64 f16 + 8 pad)
#define STAGE_BYTES (2 * BM * ROWB)     // A tile + B tile = 36864
#define GEMM_SMEM_BYTES (STAGES * STAGE_BYTES)   // 110592

// ---------------- scratch (device globals; no allocation) ----------------
__device__ __align__(128) float  g_x1 [(size_t)BT * C1];
__device__ __align__(128) __half g_qkv[(size_t)BT * C3];
__device__ __align__(128) __half g_ln1[(size_t)BT * C1];
__device__ __align__(128) __half g_att[(size_t)BT * C1];
__device__ __align__(128) __half g_ln2[(size_t)BT * C1];
__device__ __align__(128) __half g_he [(size_t)BT * C4];
__device__ __align__(128) __half g_wqkv_t[(size_t)C3 * C1];
__device__ __align__(128) __half g_wo_t  [(size_t)C1 * C1];
__device__ __align__(128) __half g_wfc_t [(size_t)C4 * C1];
__device__ __align__(128) __half g_wpr_t [(size_t)C1 * C4];

// ---------------- helpers ----------------
__device__ __forceinline__ uint32_t smem_u32(const void* p) {
    uint32_t a;
    asm("{ .reg .u64 t; cvta.to.shared.u64 t, %1; cvt.u32.u64 %0, t; }" : "=r"(a) : "l"(p));
    return a;
}
__device__ __forceinline__ void cp_async16(uint32_t saddr, const void* g) {
    asm volatile("cp.async.cg.shared.global [%0], [%1], 16;" :: "r"(saddr), "l"(g));
}
#define CP_COMMIT() asm volatile("cp.async.commit_group;" ::: "memory")
#define CP_WAIT(n)  asm volatile("cp.async.wait_group %0;" :: "n"(n) : "memory")

__device__ __forceinline__ void ldsm_x4(uint32_t* r, uint32_t addr) {
    asm volatile("ldmatrix.sync.aligned.m8n8.x4.shared.b16 {%0,%1,%2,%3}, [%4];"
        : "=r"(r[0]), "=r"(r[1]), "=r"(r[2]), "=r"(r[3]) : "r"(addr));
}
__device__ __forceinline__ void ldsm_x4_t(uint32_t* r, uint32_t addr) {
    asm volatile("ldmatrix.sync.aligned.m8n8.x4.trans.shared.b16 {%0,%1,%2,%3}, [%4];"
        : "=r"(r[0]), "=r"(r[1]), "=r"(r[2]), "=r"(r[3]) : "r"(addr));
}
__device__ __forceinline__ void mma16816(float* c, const uint32_t* a, const uint32_t* b) {
    asm volatile("mma.sync.aligned.m16n8k16.row.col.f32.f16.f16.f32 "
        "{%0,%1,%2,%3}, {%4,%5,%6,%7}, {%8,%9}, {%0,%1,%2,%3};"
        : "+f"(c[0]), "+f"(c[1]), "+f"(c[2]), "+f"(c[3])
        : "r"(a[0]), "r"(a[1]), "r"(a[2]), "r"(a[3]), "r"(b[0]), "r"(b[1]));
}
__device__ __forceinline__ uint32_t pack_h2(float a, float b) {
    __half2 h = __floats2half2_rn(a, b);
    return *(uint32_t*)&h;
}

// ---------------- weight transpose -> fp16 ----------------
// W[K,N] fp32  ->  Wt[N,K] fp16
__global__ void conv_w_kernel(const float* __restrict__ W, __half* __restrict__ Wt, int K, int N)
{
    __shared__ float tile[32][33];
    const int k0 = blockIdx.y * 32, n0 = blockIdx.x * 32;
    const int tx = threadIdx.x, ty = threadIdx.y;   // 32 x 8
#pragma unroll
    for (int i = 0; i < 32; i += 8)
        tile[ty + i][tx] = W[(long)(k0 + ty + i) * N + n0 + tx];
    __syncthreads();
#pragma unroll
    for (int i = 0; i < 32; i += 8) {
        const int n = ty + i;
        Wt[(long)(n0 + n) * K + k0 + tx] = __float2half_rn(tile[tx][n]);
    }
}

// ---------------- LayerNorm -> fp16 [row, C1] -------------
__global__ void ln_f16_kernel(const float* __restrict__ x,
                              const float* __restrict__ w,
                              const float* __restrict__ b,
                              __half* __restrict__ y)
{
    const int row = blockIdx.x;
    const float4* xr = (const float4*)(x + (size_t)row * C1);
    float4 v = xr[threadIdx.x];
    float s  = v.x + v.y + v.z + v.w;
    float s2 = v.x*v.x + v.y*v.y + v.z*v.z + v.w*v.w;
    __shared__ float red[2][8];
    for (int off = 16; off > 0; off >>= 1) {
        s  += __shfl_down_sync(0xffffffffu, s,  off);
        s2 += __shfl_down_sync(0xffffffffu, s2, off);
    }
    int warp = threadIdx.x >> 5, lane = threadIdx.x & 31;
    if (lane == 0) { red[0][warp] = s; red[1][warp] = s2; }
    __syncthreads();
    float ts = 0.f, ts2 = 0.f;
#pragma unroll
    for (int i = 0; i < 8; i++) { ts += red[0][i]; ts2 += red[1][i]; }
    float mean = ts * (1.0f / C1);
    float var  = ts2 * (1.0f / C1) - mean * mean;
    float inv  = rsqrtf(var + LN_EPS);

    const float4 wv = ((const float4*)w)[threadIdx.x];
    const float4 bv = ((const float4*)b)[threadIdx.x];
    float o0 = (v.x - mean) * inv * wv.x + bv.x;
    float o1 = (v.y - mean) * inv * wv.y + bv.y;
    float o2 = (v.z - mean) * inv * wv.z + bv.z;
    float o3 = (v.w - mean) * inv * wv.w + bv.w;
    __half2* p = (__half2*)(y + (size_t)row * C1 + threadIdx.x * 4);
    p[0] = __floats2half2_rn(o0, o1);
    p[1] = __floats2half2_rn(o2, o3);
}

// ---------------- mma.sync GEMM: D = A[M,K] @ Bt[N,K]^T + bias ----------
// EPI: 0 = fp16 out + bias; 1 = fp32 out + bias + residual; 2 = gelu -> fp16 out
template<int EPI>
__global__ void __launch_bounds__(NTH, 2)
mma_gemm(const __half* __restrict__ A,
         const __half* __restrict__ Bt,
         const float* __restrict__ bias,
         const float* __restrict__ res,
         float* __restrict__ Cf,
         __half* __restrict__ Ch,
         int N, int K)
{
    extern __shared__ char smem[];
    const uint32_t sbase = smem_u32(smem);
    const int tid  = threadIdx.x;
    const int wid  = tid >> 5, lane = tid & 31;
    const int wm   = (wid & 3) * 32;        // warp row base within tile
    const int wn   = (wid >> 2) * 64;       // warp col base within tile

    const long row0 = (long)blockIdx.y * BM;
    const long col0 = (long)blockIdx.x * BN;
    const __half* Ab = A  + row0 * K;
    const __half* Bb = Bt + col0 * K;

    const int NKB = K / BK;

    float acc[2][8][4];
#pragma unroll
    for (int mi = 0; mi < 2; mi++)
#pragma unroll
        for (int nj = 0; nj < 8; nj++)
#pragma unroll
            for (int q = 0; q < 4; q++) acc[mi][nj][q] = 0.f;

    const int grp = lane >> 3;
    const uint32_t a_off = (uint32_t)((wm + (grp & 1) * 8 + (lane & 7)) * ROWB + (grp >> 1) * 16);
    const uint32_t b_off = (uint32_t)(BM * ROWB + (wn + (grp >> 1) * 8 + (lane & 7)) * ROWB + (grp & 1) * 16);

    auto load_tile = [&](int buf, long k0) {
        const uint32_t abase = sbase + buf * STAGE_BYTES;
        const uint32_t bbase = abase + BM * ROWB;
#pragma unroll
        for (int t = 0; t < 4; t++) {
            int o = tid + t * NTH;          // 0..1023
            int r = o >> 3, seg = o & 7;
            cp_async16(abase + r * ROWB + seg * 16, Ab + (long)r * K + k0 + seg * 8);
        }
#pragma unroll
        for (int t = 0; t < 4; t++) {
            int o = tid + t * NTH;
            int r = o >> 3, seg = o & 7;
            cp_async16(bbase + r * ROWB + seg * 16, Bb + (long)r * K + k0 + seg * 8);
        }
        CP_COMMIT();
    };

#pragma unroll
    for (int s = 0; s < STAGES - 1; s++) load_tile(s, (long)s * BK);

    for (int kb = 0; kb < NKB; kb++) {
        CP_WAIT(STAGES - 2);
        __syncthreads();

        const int buf = kb % STAGES;
        const uint32_t sbuf = sbase + buf * STAGE_BYTES;

#pragma unroll
        for (int ks = 0; ks < 4; ks++) {
            uint32_t afr[2][4];
#pragma unroll
            for (int mi = 0; mi < 2; mi++)
                ldsm_x4(afr[mi], sbuf + a_off + mi * 16 * ROWB + ks * 32);
            uint32_t bfr[8][2];
#pragma unroll
            for (int njp = 0; njp < 4; njp++) {
                uint32_t t[4];
                ldsm_x4(t, sbuf + b_off + njp * 16 * ROWB + ks * 32);
                bfr[2*njp][0] = t[0]; bfr[2*njp][1] = t[1];
                bfr[2*njp+1][0] = t[2]; bfr[2*njp+1][1] = t[3];
            }
#pragma unroll
            for (int mi = 0; mi < 2; mi++)
#pragma unroll
                for (int nj = 0; nj < 8; nj++)
                    mma16816(acc[mi][nj], afr[mi], bfr[nj]);
        }

        // safe without a trailing sync: the buffer written below was last read
        // at iteration kb-1, ordered by the collective __syncthreads above.
        const int nk = kb + STAGES - 1;
        if (nk < NKB) load_tile(nk % STAGES, (long)nk * BK);
    }

    // ---- epilogue ----
#pragma unroll
    for (int mi = 0; mi < 2; mi++) {
#pragma unroll
        for (int rr = 0; rr < 2; rr++) {
            const long R = row0 + wm + mi * 16 + (lane >> 2) + rr * 8;
#pragma unroll
            for (int nj = 0; nj < 8; nj++) {
                const long CC = col0 + wn + nj * 8 + (lane & 3) * 2;
                float v0 = acc[mi][nj][rr * 2 + 0] + bias[CC];
                float v1 = acc[mi][nj][rr * 2 + 1] + bias[CC + 1];
                if (EPI == 0) {
                    *(__half2*)(Ch + R * N + CC) = __floats2half2_rn(v0, v1);
                } else if (EPI == 1) {
                    const float2 rv = *(const float2*)(res + R * N + CC);
                    *(float2*)(Cf + R * N + CC) = make_float2(v0 + rv.x, v1 + rv.y);
                } else {
                    float t0 = v0 + 0.044715f * v0 * v0 * v0;
                    float t1 = v1 + 0.044715f * v1 * v1 * v1;
                    v0 = v0 / (1.0f + __expf(-1.5957691216057308f * t0));
                    v1 = v1 / (1.0f + __expf(-1.5957691216057308f * t1));
                    *(__half2*)(Ch + R * N + CC) = __floats2half2_rn(v0, v1);
                }
            }
        }
    }
}

// ---------------- tensor-core causal flash attention (fp16 in/out) ------------
// grid (T/128, NH, B), 256 threads (8 warps x 16 q rows); 64-key tiles.
#define AROW 72   // halves per smem row (64 + 8 pad)
__global__ void __launch_bounds__(256)
attn_kernel(const __half* __restrict__ qkv, __half* __restrict__ y)
{
    const int qb = blockIdx.x, h = blockIdx.y, b = blockIdx.z;
    const int q0g = qb * 128;
    const __half* base = qkv + (size_t)b * TT * C3 + h * HD;

    __shared__ __half sq[128 * AROW];
    __shared__ __half sk[64 * AROW];
    __shared__ __half sv[64 * AROW];

    const int tid = threadIdx.x;
    const int wid = tid >> 5, lane = tid & 31;
    const int wq = wid * 16;                 // warp q-row base within 128-row block
    const int grp = lane >> 3;

    const uint32_t sqb = smem_u32(sq), skb = smem_u32(sk), svb = smem_u32(sv);

    // load Q (128 x 64 fp16)
#pragma unroll
    for (int t = 0; t < 4; t++) {
        int i = tid + t * 256;              // 0..1023
        int r = i >> 3, c8 = (i & 7) * 8;
        *(uint4*)(sq + r * AROW + c8) = *(const uint4*)(base + (size_t)(q0g + r) * C3 + c8);
    }
    __syncthreads();

    uint32_t qf[4][4];
    {
        const uint32_t qoff = (uint32_t)((wq + (grp & 1) * 8 + (lane & 7)) * AROW * 2 + (grp >> 1) * 16);
#pragma unroll
        for (int kd = 0; kd < 4; kd++)
            ldsm_x4(qf[kd], sqb + qoff + kd * 32);
    }

    float o[8][4];
#pragma unroll
    for (int i = 0; i < 8; i++)
#pragma unroll
        for (int q = 0; q < 4; q++) o[i][q] = 0.f;
    float m0 = -1e30f, m1 = -1e30f, l0 = 0.f, l1 = 0.f;

    const uint32_t kfoff = (uint32_t)(((grp >> 1) * 8 + (lane & 7)) * AROW * 2 + (grp & 1) * 16);
    const uint32_t vfoff = (uint32_t)(((grp & 1) * 8 + (lane & 7)) * AROW * 2 + (grp >> 1) * 16);

    const int nkt = 2 * qb + 2;              // key tiles 0 .. 2qb+1
    for (int kt = 0; kt < nkt; kt++) {
        __syncthreads();
        // load K, V tiles (64 x 64 each, fp16)
#pragma unroll
        for (int t = 0; t < 2; t++) {
            int i = tid + t * 256;
            int r = i >> 3, c8 = (i & 7) * 8;
            const __half* kp = base + (size_t)(kt * 64 + r) * C3 + C1 + c8;
            *(uint4*)(sk + r * AROW + c8) = *(const uint4*)kp;
            *(uint4*)(sv + r * AROW + c8) = *(const uint4*)(kp + C1);
        }
        __syncthreads();

        // warps whose rows are entirely before this key tile: skip compute
        if (kt * 64 > q0g + wq + 15) continue;

        // S = Q K^T : 16 x 64 per warp
        float c[8][4];
#pragma unroll
        for (int nj = 0; nj < 8; nj++)
#pragma unroll
            for (int q = 0; q < 4; q++) c[nj][q] = 0.f;
#pragma unroll
        for (int kd = 0; kd < 4; kd++) {
#pragma unroll
            for (int njp = 0; njp < 4; njp++) {
                uint32_t t[4];
                ldsm_x4(t, skb + kfoff + njp * 16 * AROW * 2 + kd * 32);
                uint32_t bA[2] = {t[0], t[1]}, bB[2] = {t[2], t[3]};
                mma16816(c[2*njp],   qf[kd], bA);
                mma16816(c[2*njp+1], qf[kd], bB);
            }
        }

        // scale + causal mask (tile overlapping this warp's diagonal)
        const int ra = q0g + wq + (lane >> 2);
        if (kt * 64 + 63 > ra + 8) {   // some element of this warp needs masking
#pragma unroll
            for (int nj = 0; nj < 8; nj++) {
                const int cb = kt * 64 + nj * 8 + (lane & 3) * 2;
#pragma unroll
                for (int e = 0; e < 2; e++) {
                    c[nj][e]     = (cb + e > ra)     ? -1e30f : c[nj][e] * 0.125f;
                    c[nj][2 + e] = (cb + e > ra + 8) ? -1e30f : c[nj][2 + e] * 0.125f;
                }
            }
        } else {
#pragma unroll
            for (int nj = 0; nj < 8; nj++)
#pragma unroll
                for (int q = 0; q < 4; q++) c[nj][q] *= 0.125f;
        }

        // online softmax
        float mxa = -1e30f, mxb = -1e30f;
#pragma unroll
        for (int nj = 0; nj < 8; nj++) {
            mxa = fmaxf(mxa, fmaxf(c[nj][0], c[nj][1]));
            mxb = fmaxf(mxb, fmaxf(c[nj][2], c[nj][3]));
        }
        mxa = fmaxf(mxa, __shfl_xor_sync(0xffffffffu, mxa, 1));
        mxa = fmaxf(mxa, __shfl_xor_sync(0xffffffffu, mxa, 2));
        mxb = fmaxf(mxb, __shfl_xor_sync(0xffffffffu, mxb, 1));
        mxb = fmaxf(mxb, __shfl_xor_sync(0xffffffffu, mxb, 2));
        const float mna = fmaxf(m0, mxa), mnb = fmaxf(m1, mxb);
        const float alpha_a = __expf(m0 - mna), alpha_b = __expf(m1 - mnb);
        m0 = mna; m1 = mnb;
        float suma = 0.f, sumb = 0.f;
#pragma unroll
        for (int nj = 0; nj < 8; nj++) {
            c[nj][0] = __expf(c[nj][0] - mna);
            c[nj][1] = __expf(c[nj][1] - mna);
            c[nj][2] = __expf(c[nj][2] - mnb);
            c[nj][3] = __expf(c[nj][3] - mnb);
            suma += c[nj][0] + c[nj][1];
            sumb += c[nj][2] + c[nj][3];
        }
        suma += __shfl_xor_sync(0xffffffffu, suma, 1);
        suma += __shfl_xor_sync(0xffffffffu, suma, 2);
        sumb += __shfl_xor_sync(0xffffffffu, sumb, 1);
        sumb += __shfl_xor_sync(0xffffffffu, sumb, 2);
        l0 = l0 * alpha_a + suma;
        l1 = l1 * alpha_b + sumb;
#pragma unroll
        for (int i = 0; i < 8; i++) {
            o[i][0] *= alpha_a; o[i][1] *= alpha_a;
            o[i][2] *= alpha_b; o[i][3] *= alpha_b;
        }

        // P fragments
        uint32_t pf[4][4];
#pragma unroll
        for (int ks = 0; ks < 4; ks++) {
            pf[ks][0] = pack_h2(c[2*ks][0],   c[2*ks][1]);
            pf[ks][1] = pack_h2(c[2*ks][2],   c[2*ks][3]);
            pf[ks][2] = pack_h2(c[2*ks+1][0], c[2*ks+1][1]);
            pf[ks][3] = pack_h2(c[2*ks+1][2], c[2*ks+1][3]);
        }

        // O += P @ V
#pragma unroll
        for (int ks = 0; ks < 4; ks++) {
#pragma unroll
            for (int dp = 0; dp < 4; dp++) {
                uint32_t t[4];
                ldsm_x4_t(t, svb + vfoff + ks * 16 * AROW * 2 + dp * 32);
                uint32_t bA[2] = {t[0], t[1]}, bB[2] = {t[2], t[3]};
                mma16816(o[2*dp],   pf[ks], bA);
                mma16816(o[2*dp+1], pf[ks], bB);
            }
        }
    }

    // epilogue: divide by l, plain fp16 out [BT, C1]
    const float invl0 = 1.0f / l0, invl1 = 1.0f / l1;
    const long rowg = (long)b * TT + q0g + wq + (lane >> 2);
#pragma unroll
    for (int i = 0; i < 8; i++) {
        const int colg = h * HD + i * 8 + (lane & 3) * 2;
        *(__half2*)(y + rowg * C1 + colg)       = __floats2half2_rn(o[i][0] * invl0, o[i][1] * invl0);
        *(__half2*)(y + (rowg + 8) * C1 + colg) = __floats2half2_rn(o[i][2] * invl1, o[i][3] * invl1);
    }
}

// ---------------- launcher ----------------
extern "C" void kernel_launch(void* const* d_in, const int* in_sizes, int n_in,
                              void* d_out, int out_size)
{
    const float* x      = (const float*)d_in[0];
    const float* ln1_w  = (const float*)d_in[1];
    const float* ln1_b  = (const float*)d_in[2];
    const float* w_qkv  = (const float*)d_in[3];
    const float* b_qkv  = (const float*)d_in[4];
    const float* w_o    = (const float*)d_in[5];
    const float* b_o    = (const float*)d_in[6];
    const float* ln2_w  = (const float*)d_in[7];
    const float* ln2_b  = (const float*)d_in[8];
    const float* w_fc   = (const float*)d_in[9];
    const float* b_fc   = (const float*)d_in[10];
    const float* w_proj = (const float*)d_in[11];
    const float* b_proj = (const float*)d_in[12];
    float* out = (float*)d_out;

    float* x1;
    __half *qkv, *ln1, *att, *ln2, *he, *wqkv_t, *wo_t, *wfc_t, *wpr_t;
    cudaGetSymbolAddress((void**)&x1,   g_x1);
    cudaGetSymbolAddress((void**)&qkv,  g_qkv);
    cudaGetSymbolAddress((void**)&ln1,  g_ln1);
    cudaGetSymbolAddress((void**)&att,  g_att);
    cudaGetSymbolAddress((void**)&ln2,  g_ln2);
    cudaGetSymbolAddress((void**)&he,   g_he);
    cudaGetSymbolAddress((void**)&wqkv_t, g_wqkv_t);
    cudaGetSymbolAddress((void**)&wo_t,   g_wo_t);
    cudaGetSymbolAddress((void**)&wfc_t,  g_wfc_t);
    cudaGetSymbolAddress((void**)&wpr_t,  g_wpr_t);

    cudaFuncSetAttribute(mma_gemm<0>, cudaFuncAttributeMaxDynamicSharedMemorySize, GEMM_SMEM_BYTES);
    cudaFuncSetAttribute(mma_gemm<1>, cudaFuncAttributeMaxDynamicSharedMemorySize, GEMM_SMEM_BYTES);
    cudaFuncSetAttribute(mma_gemm<2>, cudaFuncAttributeMaxDynamicSharedMemorySize, GEMM_SMEM_BYTES);

    // Launch order arranged so ncu (-s 5 -c 1) lands on a heavy kernel:
    // 0: conv_w(qkv)  1: ln1  2: QKV gemm  3: conv_w(o)  4: attention
    // 5: O-proj gemm  6: ln2  7: conv_w(fc) 8: FC gemm   9: conv_w(proj) 10: down-proj
    conv_w_kernel<<<dim3(C3 / 32, C1 / 32), dim3(32, 8)>>>(w_qkv,  wqkv_t, C1, C3);
    ln_f16_kernel<<<BT, 256>>>(x, ln1_w, ln1_b, ln1);
    mma_gemm<0><<<dim3(C3 / BN, BT / BM), NTH, GEMM_SMEM_BYTES>>>(ln1, wqkv_t, b_qkv, nullptr, nullptr, qkv, C3, C1);
    conv_w_kernel<<<dim3(C1 / 32, C1 / 32), dim3(32, 8)>>>(w_o,    wo_t,   C1, C1);
    attn_kernel<<<dim3(TT / 128, NH, BB), 256>>>(qkv, att);
    mma_gemm<1><<<dim3(C1 / BN, BT / BM), NTH, GEMM_SMEM_BYTES>>>(att, wo_t, b_o, x, x1, nullptr, C1, C1);
    ln_f16_kernel<<<BT, 256>>>(x1, ln2_w, ln2_b, ln2);
    conv_w_kernel<<<dim3(C4 / 32, C1 / 32), dim3(32, 8)>>>(w_fc,   wfc_t,  C1, C4);
    mma_gemm<2><<<dim3(C4 / BN, BT / BM), NTH, GEMM_SMEM_BYTES>>>(ln2, wfc_t, b_fc, nullptr, nullptr, he, C4, C1);
    conv_w_kernel<<<dim3(C1 / 32, C4 / 32), dim3(32, 8)>>>(w_proj, wpr_t,  C4, C1);
    mma_gemm<1><<<dim3(C1 / BN, BT / BM), NTH, GEMM_SMEM_BYTES>>>(he, wpr_t, b_proj, x1, out, nullptr, C1, C4);
}